// round 9
// baseline (speedup 1.0000x reference)
#include <cuda_runtime.h>
#include <cuda.h>
#include <cuda_fp16.h>
#include <cstdint>
#include <cstddef>

// ---------------- problem dims ----------------
#define DIN   4096
#define DOUT  4096
#define MTOT  16384            // B_SZ * S
#define KLORA 256              // E * R

#define BK 64                  // 64 fp16 = 128B row = SW128 atom
#define SMEM_CTRL 1024

// Both GEMMs: 128x128 CTA tile, 4 compute warps (64x64 each) + producer,
// 3 stages, 2 CTAs co-resident per SM.
#define BMX 128
#define BNX 128
#define NSTG 3
#define NCW 4
#define NTHREADS 160
#define SMEM_TOTAL (SMEM_CTRL + NSTG * (BMX + BNX) * BK * 2)   // 99328

// ---------------- scratch (device globals; no allocation allowed) ----------
__device__ __align__(256) __half g_xh[(size_t)MTOT * DIN];   // 128 MB fp16 x
__device__ __align__(256) __half g_wh[(size_t)DOUT * DIN];   //  32 MB fp16 W_eff
__device__ __align__(256) __half g_cm[(size_t)DOUT * KLORA]; //   2 MB probs*B
__device__ __align__(256) __half g_at[(size_t)DIN * KLORA];  //   2 MB A^T

// ---------------- PTX helpers ----------------
__device__ __forceinline__ uint32_t smem_u32(const void* p) {
    uint32_t a;
    asm("{ .reg .u64 t; cvta.to.shared.u64 t, %1; cvt.u32.u64 %0, t; }"
        : "=r"(a) : "l"(p));
    return a;
}

#define MBARRIER_INIT(addr, cnt) \
    asm volatile("mbarrier.init.shared.b64 [%0], %1;" \
                 :: "r"((uint32_t)(addr)), "r"((uint32_t)(cnt)) : "memory")

#define MBARRIER_EXPECT_TX(addr, bytes) \
    asm volatile("mbarrier.arrive.expect_tx.shared.b64 _, [%0], %1;" \
                 :: "r"((uint32_t)(addr)), "r"((uint32_t)(bytes)) : "memory")

#define MBARRIER_ARRIVE(addr) \
    asm volatile("mbarrier.arrive.shared.b64 _, [%0];" \
                 :: "r"((uint32_t)(addr)) : "memory")

#define MBARRIER_WAIT_PARITY(addr, parity) do { \
    uint32_t _mb = (uint32_t)(addr); \
    uint32_t _pa = (uint32_t)(parity); \
    asm volatile( \
        "{\n\t.reg .pred P1;\n\t" \
        "WL_%=:\n\t" \
        "mbarrier.try_wait.parity.shared.b64 P1, [%0], %1;\n\t" \
        "@P1 bra.uni WD_%=;\n\t" \
        "bra.uni WL_%=;\n\t" \
        "WD_%=:\n\t}" \
        :: "r"(_mb), "r"(_pa) : "memory"); \
} while (0)

#define TMA2D(sa, pmap, cx, cy, mb) \
    asm volatile("cp.async.bulk.tensor.2d.shared::cta.global.tile.mbarrier::complete_tx::bytes " \
                 "[%0], [%1, {%2, %3}], [%4];" \
                 :: "r"((uint32_t)(sa)), "l"(pmap), "r"((int)(cx)), "r"((int)(cy)), \
                    "r"((uint32_t)(mb)) : "memory")

__device__ __forceinline__ void ldsm4(uint32_t* r, uint32_t a) {
    asm volatile("ldmatrix.sync.aligned.m8n8.x4.shared.b16 {%0,%1,%2,%3}, [%4];"
                 : "=r"(r[0]), "=r"(r[1]), "=r"(r[2]), "=r"(r[3]) : "r"(a));
}

__device__ __forceinline__ void mma16816(float* c, const uint32_t* a,
                                         uint32_t b0, uint32_t b1) {
    asm volatile("mma.sync.aligned.m16n8k16.row.col.f32.f16.f16.f32 "
                 "{%0,%1,%2,%3}, {%4,%5,%6,%7}, {%8,%9}, {%0,%1,%2,%3};"
                 : "+f"(c[0]), "+f"(c[1]), "+f"(c[2]), "+f"(c[3])
                 : "r"(a[0]), "r"(a[1]), "r"(a[2]), "r"(a[3]), "r"(b0), "r"(b1));
}

#define BAR_FULL(s)  (sb + 16 + (uint32_t)(s) * 16)
#define BAR_EMPTY(s) (sb + 24 + (uint32_t)(s) * 16)

// ======================================================================
// GEMM: out[M][N] = Aop[M][K] @ Bop[N][K]^T, fp16 ops / fp32 acc.
//   + addM[M][N] (if non-null) else + bias[N];  outHalf selects output type.
// 128x128 CTA tile: 4 compute warps (2x2 of 64x64) + 1 TMA producer warp.
// 3-stage TMA pipeline; 2 CTAs co-resident per SM.
// grid: (N/128, M/128).
// ======================================================================
__global__ __launch_bounds__(NTHREADS, 2) void gemm_fp16(
    const __grid_constant__ CUtensorMap tmA,
    const __grid_constant__ CUtensorMap tmB,
    void* __restrict__ outp,
    const float* __restrict__ addM,
    const float* __restrict__ bias,
    int kstages, int ncols, int outHalf)
{
    constexpr int ABYT = BMX * BK * 2;          // 16384
    constexpr int STGB = (BMX + BNX) * BK * 2;  // 32768

    extern __shared__ char smem[];
    uint32_t sb = smem_u32(smem);
    int tid = threadIdx.x, wid = tid >> 5, lane = tid & 31;

    if (tid == 0) {
        #pragma unroll
        for (int s = 0; s < NSTG; s++) {
            MBARRIER_INIT(BAR_FULL(s), 1);
            MBARRIER_INIT(BAR_EMPTY(s), NCW);
        }
    }
    __syncthreads();

    if (wid == NCW) {
        // ---------------- TMA producer (lane 0 only) ----------------
        if (lane == 0) {
            const CUtensorMap* pA = &tmA;
            const CUtensorMap* pB = &tmB;
            int st = 0, ph = 1;
            int my = blockIdx.y * BMX, nx = blockIdx.x * BNX;
            for (int s = 0; s < kstages; s++) {
                MBARRIER_WAIT_PARITY(BAR_EMPTY(st), ph);
                MBARRIER_EXPECT_TX(BAR_FULL(st), STGB);
                uint32_t ab = sb + SMEM_CTRL + st * STGB;
                TMA2D(ab,        pA, s * BK, my, BAR_FULL(st));
                TMA2D(ab + ABYT, pB, s * BK, nx, BAR_FULL(st));
                if (++st == NSTG) { st = 0; ph ^= 1; }
            }
        }
        return;
    }

    // ------- compute warps: 2(M) x 2(N) grid of 64(M) x 64(N) tiles -------
    int wr = wid & 1;           // M offset 64*wr
    int wc = wid >> 1;          // N offset 64*wc
    int r15 = lane & 15, kh = lane >> 4;

    // per-lane ldmatrix row offsets + SW128 XOR terms (row bits only;
    // k-offset bits [4:6] never reach the swizzle field)
    uint32_t aPre[4], aX[4], bPre[4], bX[4];
    #pragma unroll
    for (int t = 0; t < 4; t++) {
        uint32_t arow = (uint32_t)(64 * wr + 16 * t + r15) * 128u;
        aPre[t] = arow;
        aX[t] = (arow >> 3) & 0x70u;
        uint32_t brow = (uint32_t)(64 * wc + 16 * t + r15) * 128u;
        bPre[t] = ABYT + brow;
        bX[t] = (brow >> 3) & 0x70u;
    }
    uint32_t khb = (uint32_t)kh << 4;    // 16B per 8-fp16 k-half

    float c[4][8][4];
    #pragma unroll
    for (int mt = 0; mt < 4; mt++)
        #pragma unroll
        for (int nt = 0; nt < 8; nt++)
            #pragma unroll
            for (int e = 0; e < 4; e++) c[mt][nt][e] = 0.0f;

    int st = 0, ph = 0;
    for (int s = 0; s < kstages; s++) {
        MBARRIER_WAIT_PARITY(BAR_FULL(st), ph);
        uint32_t stbase = sb + SMEM_CTRL + (uint32_t)st * STGB;

        #pragma unroll
        for (int kk = 0; kk < 4; kk++) {
            uint32_t kbits = ((uint32_t)kk << 5) | khb;   // kk*32 + kh*16 bytes
            uint32_t af[4][4], bf[4][4];
            #pragma unroll
            for (int mt = 0; mt < 4; mt++)
                ldsm4(af[mt], stbase + aPre[mt] + (kbits ^ aX[mt]));
            #pragma unroll
            for (int nt = 0; nt < 4; nt++)
                ldsm4(bf[nt], stbase + bPre[nt] + (kbits ^ bX[nt]));
            #pragma unroll
            for (int mt = 0; mt < 4; mt++)
                #pragma unroll
                for (int n8 = 0; n8 < 8; n8++)
                    mma16816(c[mt][n8], af[mt],
                             bf[n8 >> 1][n8 & 1], bf[n8 >> 1][(n8 & 1) + 2]);
        }
        if (lane == 0) MBARRIER_ARRIVE(BAR_EMPTY(st));
        if (++st == NSTG) { st = 0; ph ^= 1; }
    }

    // ---------------- epilogue: direct store from fragments ----------------
    int mbase = blockIdx.y * BMX + 64 * wr;
    int nbase = blockIdx.x * BNX + 64 * wc;
    int frow = lane >> 2, fcol = (lane & 3) * 2;

    #pragma unroll
    for (int mt = 0; mt < 4; mt++) {
        int r0 = mbase + 16 * mt + frow;
        #pragma unroll
        for (int n8 = 0; n8 < 8; n8++) {
            int gc = nbase + 8 * n8 + fcol;
            float add0a, add1a, add0b, add1b;
            if (addM) {
                const float2 wa = *reinterpret_cast<const float2*>(
                    &addM[(size_t)r0 * ncols + gc]);
                const float2 wb = *reinterpret_cast<const float2*>(
                    &addM[(size_t)(r0 + 8) * ncols + gc]);
                add0a = wa.x; add1a = wa.y; add0b = wb.x; add1b = wb.y;
            } else {
                const float2 bb = *reinterpret_cast<const float2*>(&bias[gc]);
                add0a = bb.x; add1a = bb.y; add0b = bb.x; add1b = bb.y;
            }
            float v0 = c[mt][n8][0] + add0a;
            float v1 = c[mt][n8][1] + add1a;
            float v2 = c[mt][n8][2] + add0b;
            float v3 = c[mt][n8][3] + add1b;
            if (outHalf) {
                __half2* oh = (__half2*)outp;
                oh[((size_t)r0 * ncols + gc) >> 1]       = __floats2half2_rn(v0, v1);
                oh[((size_t)(r0 + 8) * ncols + gc) >> 1] = __floats2half2_rn(v2, v3);
            } else {
                float* of = (float*)outp;
                *reinterpret_cast<float2*>(&of[(size_t)r0 * ncols + gc]) =
                    make_float2(v0, v1);
                *reinterpret_cast<float2*>(&of[(size_t)(r0 + 8) * ncols + gc]) =
                    make_float2(v2, v3);
            }
        }
    }
}

// ======================================================================
// prep kernels
// ======================================================================
__global__ void k_x2h(const float4* __restrict__ in, __half2* __restrict__ o, int n4) {
    int i = blockIdx.x * blockDim.x + threadIdx.x;
    if (i < n4) {
        float4 v = in[i];
        o[2 * i]     = __floats2half2_rn(v.x, v.y);
        o[2 * i + 1] = __floats2half2_rn(v.z, v.w);
    }
}

// merged: Cm[o][er] = h(probs[e]*B[e][o][r]);  At[d][er] = h(A[er][d])
__global__ void k_prep(const float* __restrict__ Bw, const float* __restrict__ probs,
                       const float* __restrict__ A,
                       __half* __restrict__ Cm, __half* __restrict__ At) {
    int idx = blockIdx.x * blockDim.x + threadIdx.x;
    if (idx < DOUT * KLORA) {
        int er = idx & 255, o = idx >> 8;
        int e = er >> 4, r = er & 15;
        Cm[idx] = __float2half_rn(probs[e] * Bw[((size_t)e * DOUT + o) * 16 + r]);
    } else {
        int j = idx - DOUT * KLORA;
        if (j < DIN * KLORA) {
            int d = j & 4095, er = j >> 12;
            At[(size_t)d * KLORA + er] = __float2half_rn(A[(size_t)er * DIN + d]);
        }
    }
}

// ======================================================================
// host side
// ======================================================================
typedef CUresult (*PFN_encodeTiled)(
    CUtensorMap*, CUtensorMapDataType, cuuint32_t, void*,
    const cuuint64_t*, const cuuint64_t*, const cuuint32_t*, const cuuint32_t*,
    CUtensorMapInterleave, CUtensorMapSwizzle, CUtensorMapL2promotion,
    CUtensorMapFloatOOBfill);

static void make_map(PFN_encodeTiled enc, CUtensorMap* m, void* base,
                     unsigned long long kdim, unsigned long long rows,
                     unsigned boxrows) {
    cuuint64_t dims[2]    = {kdim, rows};
    cuuint64_t strides[1] = {kdim * 2};               // fp16
    cuuint32_t box[2]     = {(cuuint32_t)BK, boxrows};
    cuuint32_t es[2]      = {1u, 1u};
    enc(m, CU_TENSOR_MAP_DATA_TYPE_FLOAT16, 2, base, dims, strides, box, es,
        CU_TENSOR_MAP_INTERLEAVE_NONE, CU_TENSOR_MAP_SWIZZLE_128B,
        CU_TENSOR_MAP_L2_PROMOTION_L2_128B, CU_TENSOR_MAP_FLOAT_OOB_FILL_NONE);
}

extern "C" void kernel_launch(void* const* d_in, const int* in_sizes, int n_in,
                              void* d_out, int out_size) {
    const float* x     = (const float*)d_in[0];
    const float* W     = (const float*)d_in[1];
    const float* b     = (const float*)d_in[2];
    const float* A     = (const float*)d_in[3];
    const float* Bw    = (const float*)d_in[4];
    const float* probs = (const float*)d_in[5];

    __half *xh, *wh, *cm, *at;
    cudaGetSymbolAddress((void**)&xh, g_xh);
    cudaGetSymbolAddress((void**)&wh, g_wh);
    cudaGetSymbolAddress((void**)&cm, g_cm);
    cudaGetSymbolAddress((void**)&at, g_at);

    void* fp = nullptr;
    cudaDriverEntryPointQueryResult qr;
    cudaGetDriverEntryPointByVersion("cuTensorMapEncodeTiled", &fp, 12000,
                                     cudaEnableDefault, &qr);
    PFN_encodeTiled enc = (PFN_encodeTiled)fp;

    CUtensorMap mapX, mapWh, mapC, mapAt;
    make_map(enc, &mapX,  xh, DIN,   MTOT, BMX);   // A of GEMM2
    make_map(enc, &mapWh, wh, DIN,   DOUT, BNX);   // B of GEMM2
    make_map(enc, &mapC,  cm, KLORA, DOUT, BMX);   // A of GEMM1
    make_map(enc, &mapAt, at, KLORA, DIN,  BNX);   // B of GEMM1

    cudaFuncSetAttribute(gemm_fp16, cudaFuncAttributeMaxDynamicSharedMemorySize,
                         SMEM_TOTAL);

    // lazily create side stream + fork/join events on the first (uncaptured)
    // call; replays reuse them so every call does identical work.
    static bool s_init = false;
    static cudaStream_t s_side = 0;
    static cudaEvent_t s_eF = 0, s_eJ = 0;
    if (!s_init) {
        s_init = true;
        if (cudaStreamCreateWithFlags(&s_side, cudaStreamNonBlocking) != cudaSuccess)
            s_side = 0;
        if (s_side) {
            cudaEventCreateWithFlags(&s_eF, cudaEventDisableTiming);
            cudaEventCreateWithFlags(&s_eJ, cudaEventDisableTiming);
        }
    }

    int n4 = (MTOT * DIN) / 4;
    int prepN = (DOUT * KLORA + DIN * KLORA + 255) / 256;

    if (s_side) {
        // fork: x -> fp16 on side stream; LoRA prep + W_eff GEMM on main
        cudaEventRecord(s_eF, 0);
        cudaStreamWaitEvent(s_side, s_eF, 0);
        k_x2h<<<n4 / 256, 256, 0, s_side>>>((const float4*)x, (__half2*)xh, n4);
        cudaEventRecord(s_eJ, s_side);

        k_prep<<<prepN, 256>>>(Bw, probs, A, cm, at);
        gemm_fp16<<<dim3(DIN / BNX, DOUT / BMX), NTHREADS, SMEM_TOTAL>>>(
            mapC, mapAt, wh, W, nullptr, KLORA / BK, DIN, 1);

        cudaStreamWaitEvent(0, s_eJ, 0);   // join before the big GEMM
    } else {
        k_x2h<<<n4 / 256, 256>>>((const float4*)x, (__half2*)xh, n4);
        k_prep<<<prepN, 256>>>(Bw, probs, A, cm, at);
        gemm_fp16<<<dim3(DIN / BNX, DOUT / BMX), NTHREADS, SMEM_TOTAL>>>(
            mapC, mapAt, wh, W, nullptr, KLORA / BK, DIN, 1);
    }

    // out = xh @ W_eff^T + b   [M=16384, N=4096, K=4096]
    gemm_fp16<<<dim3(DOUT / BNX, MTOT / BMX), NTHREADS, SMEM_TOTAL>>>(
        mapX, mapWh, d_out, nullptr, b, DIN / BK, DOUT, 0);
}

// round 10
// speedup vs baseline: 1.0144x; 1.0144x over previous
#include <cuda_runtime.h>
#include <cuda.h>
#include <cuda_fp16.h>
#include <cstdint>
#include <cstddef>

// ---------------- problem dims ----------------
#define DIN   4096
#define DOUT  4096
#define MTOT  16384            // B_SZ * S
#define MHALF (MTOT / 2)       // 8192
#define KLORA 256              // E * R

#define BK 64                  // 64 fp16 = 128B row = SW128 atom
#define SMEM_CTRL 1024

// Both GEMMs: 128x128 CTA tile, 8 compute warps + producer, 3 stages,
// 2 CTAs co-resident per SM.
#define BMX 128
#define BNX 128
#define NSTG 3
#define NCW 8
#define NTHREADS 288
#define SMEM_TOTAL (SMEM_CTRL + NSTG * (BMX + BNX) * BK * 2)   // 99328

// ---------------- scratch (device globals; no allocation allowed) ----------
__device__ __align__(256) __half g_xh[(size_t)MTOT * DIN];   // 128 MB fp16 x
__device__ __align__(256) __half g_wh[(size_t)DOUT * DIN];   //  32 MB fp16 W_eff
__device__ __align__(256) __half g_cm[(size_t)DOUT * KLORA]; //   2 MB probs*B
__device__ __align__(256) __half g_at[(size_t)DIN * KLORA];  //   2 MB A^T

// ---------------- PTX helpers ----------------
__device__ __forceinline__ uint32_t smem_u32(const void* p) {
    uint32_t a;
    asm("{ .reg .u64 t; cvta.to.shared.u64 t, %1; cvt.u32.u64 %0, t; }"
        : "=r"(a) : "l"(p));
    return a;
}

#define MBARRIER_INIT(addr, cnt) \
    asm volatile("mbarrier.init.shared.b64 [%0], %1;" \
                 :: "r"((uint32_t)(addr)), "r"((uint32_t)(cnt)) : "memory")

#define MBARRIER_EXPECT_TX(addr, bytes) \
    asm volatile("mbarrier.arrive.expect_tx.shared.b64 _, [%0], %1;" \
                 :: "r"((uint32_t)(addr)), "r"((uint32_t)(bytes)) : "memory")

#define MBARRIER_ARRIVE(addr) \
    asm volatile("mbarrier.arrive.shared.b64 _, [%0];" \
                 :: "r"((uint32_t)(addr)) : "memory")

#define MBARRIER_WAIT_PARITY(addr, parity) do { \
    uint32_t _mb = (uint32_t)(addr); \
    uint32_t _pa = (uint32_t)(parity); \
    asm volatile( \
        "{\n\t.reg .pred P1;\n\t" \
        "WL_%=:\n\t" \
        "mbarrier.try_wait.parity.shared.b64 P1, [%0], %1;\n\t" \
        "@P1 bra.uni WD_%=;\n\t" \
        "bra.uni WL_%=;\n\t" \
        "WD_%=:\n\t}" \
        :: "r"(_mb), "r"(_pa) : "memory"); \
} while (0)

#define TMA2D(sa, pmap, cx, cy, mb) \
    asm volatile("cp.async.bulk.tensor.2d.shared::cta.global.tile.mbarrier::complete_tx::bytes " \
                 "[%0], [%1, {%2, %3}], [%4];" \
                 :: "r"((uint32_t)(sa)), "l"(pmap), "r"((int)(cx)), "r"((int)(cy)), \
                    "r"((uint32_t)(mb)) : "memory")

__device__ __forceinline__ void ldsm4(uint32_t* r, uint32_t a) {
    asm volatile("ldmatrix.sync.aligned.m8n8.x4.shared.b16 {%0,%1,%2,%3}, [%4];"
                 : "=r"(r[0]), "=r"(r[1]), "=r"(r[2]), "=r"(r[3]) : "r"(a));
}

__device__ __forceinline__ void mma16816(float* c, const uint32_t* a,
                                         uint32_t b0, uint32_t b1) {
    asm volatile("mma.sync.aligned.m16n8k16.row.col.f32.f16.f16.f32 "
                 "{%0,%1,%2,%3}, {%4,%5,%6,%7}, {%8,%9}, {%0,%1,%2,%3};"
                 : "+f"(c[0]), "+f"(c[1]), "+f"(c[2]), "+f"(c[3])
                 : "r"(a[0]), "r"(a[1]), "r"(a[2]), "r"(a[3]), "r"(b0), "r"(b1));
}

#define BAR_FULL(s)  (sb + 16 + (uint32_t)(s) * 16)
#define BAR_EMPTY(s) (sb + 24 + (uint32_t)(s) * 16)

// ======================================================================
// GEMM: out[M][N] = Aop[M][K] @ Bop[N][K]^T, fp16 ops / fp32 acc.
//   + addM[M][N] (if non-null) else + bias[N];  outHalf selects output type.
// 128x128 CTA tile: 8 compute warps (2(M) x 4(N) of 64x32) + 1 TMA producer.
// 3-stage TMA pipeline; 2 CTAs co-resident per SM.
// grid: (N/128, M/128).
// ======================================================================
__global__ __launch_bounds__(NTHREADS, 2) void gemm_fp16(
    const __grid_constant__ CUtensorMap tmA,
    const __grid_constant__ CUtensorMap tmB,
    void* __restrict__ outp,
    const float* __restrict__ addM,
    const float* __restrict__ bias,
    int kstages, int ncols, int outHalf)
{
    constexpr int ABYT = BMX * BK * 2;          // 16384
    constexpr int STGB = (BMX + BNX) * BK * 2;  // 32768

    extern __shared__ char smem[];
    uint32_t sb = smem_u32(smem);
    int tid = threadIdx.x, wid = tid >> 5, lane = tid & 31;

    if (tid == 0) {
        #pragma unroll
        for (int s = 0; s < NSTG; s++) {
            MBARRIER_INIT(BAR_FULL(s), 1);
            MBARRIER_INIT(BAR_EMPTY(s), NCW);
        }
    }
    __syncthreads();

    if (wid == NCW) {
        // ---------------- TMA producer (lane 0 only) ----------------
        if (lane == 0) {
            const CUtensorMap* pA = &tmA;
            const CUtensorMap* pB = &tmB;
            int st = 0, ph = 1;
            int my = blockIdx.y * BMX, nx = blockIdx.x * BNX;
            for (int s = 0; s < kstages; s++) {
                MBARRIER_WAIT_PARITY(BAR_EMPTY(st), ph);
                MBARRIER_EXPECT_TX(BAR_FULL(st), STGB);
                uint32_t ab = sb + SMEM_CTRL + st * STGB;
                TMA2D(ab,        pA, s * BK, my, BAR_FULL(st));
                TMA2D(ab + ABYT, pB, s * BK, nx, BAR_FULL(st));
                if (++st == NSTG) { st = 0; ph ^= 1; }
            }
        }
        return;
    }

    // ------- compute warps: 2(M) x 4(N) grid of 64(M) x 32(N) tiles -------
    int wr = wid & 1;           // M offset 64*wr   (0..1)
    int wc = wid >> 1;          // N offset 32*wc   (0..3)
    int r15 = lane & 15, kh = lane >> 4;

    // per-lane ldmatrix row offsets + SW128 XOR terms (row bits only;
    // k-offset bits [4:6] never reach the swizzle field)
    uint32_t aPre[4], aX[4], bPre[2], bX[2];
    #pragma unroll
    for (int t = 0; t < 4; t++) {
        uint32_t arow = (uint32_t)(64 * wr + 16 * t + r15) * 128u;
        aPre[t] = arow;
        aX[t] = (arow >> 3) & 0x70u;
    }
    #pragma unroll
    for (int t = 0; t < 2; t++) {
        uint32_t brow = (uint32_t)(32 * wc + 16 * t + r15) * 128u;
        bPre[t] = ABYT + brow;
        bX[t] = (brow >> 3) & 0x70u;
    }
    uint32_t khb = (uint32_t)kh << 4;    // 16B per 8-fp16 k-half

    float c[4][4][4];
    #pragma unroll
    for (int mt = 0; mt < 4; mt++)
        #pragma unroll
        for (int nt = 0; nt < 4; nt++)
            #pragma unroll
            for (int e = 0; e < 4; e++) c[mt][nt][e] = 0.0f;

    uint32_t af[2][4][4];      // double-buffered A fragments
    uint32_t bf[2][4];

    int st = 0, ph = 0;
    for (int s = 0; s < kstages; s++) {
        MBARRIER_WAIT_PARITY(BAR_FULL(st), ph);
        uint32_t stbase = sb + SMEM_CTRL + (uint32_t)st * STGB;

        {
            uint32_t kbits = khb;
            #pragma unroll
            for (int mt = 0; mt < 4; mt++)
                ldsm4(af[0][mt], stbase + aPre[mt] + (kbits ^ aX[mt]));
        }
        #pragma unroll
        for (int kk = 0; kk < 4; kk++) {
            int cur = kk & 1;
            uint32_t kbits = ((uint32_t)kk << 5) | khb;
            if (kk < 3) {
                uint32_t kb2 = ((uint32_t)(kk + 1) << 5) | khb;
                #pragma unroll
                for (int mt = 0; mt < 4; mt++)
                    ldsm4(af[cur ^ 1][mt], stbase + aPre[mt] + (kb2 ^ aX[mt]));
            }
            #pragma unroll
            for (int nt = 0; nt < 2; nt++)
                ldsm4(bf[nt], stbase + bPre[nt] + (kbits ^ bX[nt]));
            #pragma unroll
            for (int mt = 0; mt < 4; mt++)
                #pragma unroll
                for (int n8 = 0; n8 < 4; n8++)
                    mma16816(c[mt][n8], af[cur][mt],
                             bf[n8 >> 1][n8 & 1], bf[n8 >> 1][(n8 & 1) + 2]);
        }
        if (lane == 0) MBARRIER_ARRIVE(BAR_EMPTY(st));
        if (++st == NSTG) { st = 0; ph ^= 1; }
    }

    // ---------------- epilogue: direct store from fragments ----------------
    int mbase = blockIdx.y * BMX + 64 * wr;
    int nbase = blockIdx.x * BNX + 32 * wc;
    int frow = lane >> 2, fcol = (lane & 3) * 2;

    #pragma unroll
    for (int mt = 0; mt < 4; mt++) {
        int r0 = mbase + 16 * mt + frow;
        #pragma unroll
        for (int n8 = 0; n8 < 4; n8++) {
            int gc = nbase + 8 * n8 + fcol;
            float add0a, add1a, add0b, add1b;
            if (addM) {
                const float2 wa = *reinterpret_cast<const float2*>(
                    &addM[(size_t)r0 * ncols + gc]);
                const float2 wb = *reinterpret_cast<const float2*>(
                    &addM[(size_t)(r0 + 8) * ncols + gc]);
                add0a = wa.x; add1a = wa.y; add0b = wb.x; add1b = wb.y;
            } else {
                const float2 bb = *reinterpret_cast<const float2*>(&bias[gc]);
                add0a = bb.x; add1a = bb.y; add0b = bb.x; add1b = bb.y;
            }
            float v0 = c[mt][n8][0] + add0a;
            float v1 = c[mt][n8][1] + add1a;
            float v2 = c[mt][n8][2] + add0b;
            float v3 = c[mt][n8][3] + add1b;
            if (outHalf) {
                __half2* oh = (__half2*)outp;
                oh[((size_t)r0 * ncols + gc) >> 1]       = __floats2half2_rn(v0, v1);
                oh[((size_t)(r0 + 8) * ncols + gc) >> 1] = __floats2half2_rn(v2, v3);
            } else {
                float* of = (float*)outp;
                *reinterpret_cast<float2*>(&of[(size_t)r0 * ncols + gc]) =
                    make_float2(v0, v1);
                *reinterpret_cast<float2*>(&of[(size_t)(r0 + 8) * ncols + gc]) =
                    make_float2(v2, v3);
            }
        }
    }
}

// ======================================================================
// prep kernels
// ======================================================================
__global__ void k_x2h(const float4* __restrict__ in, __half2* __restrict__ o, int n4) {
    int i = blockIdx.x * blockDim.x + threadIdx.x;
    if (i < n4) {
        float4 v = in[i];
        o[2 * i]     = __floats2half2_rn(v.x, v.y);
        o[2 * i + 1] = __floats2half2_rn(v.z, v.w);
    }
}

// merged: Cm[o][er] = h(probs[e]*B[e][o][r]);  At[d][er] = h(A[er][d])
__global__ void k_prep(const float* __restrict__ Bw, const float* __restrict__ probs,
                       const float* __restrict__ A,
                       __half* __restrict__ Cm, __half* __restrict__ At) {
    int idx = blockIdx.x * blockDim.x + threadIdx.x;
    if (idx < DOUT * KLORA) {
        int er = idx & 255, o = idx >> 8;
        int e = er >> 4, r = er & 15;
        Cm[idx] = __float2half_rn(probs[e] * Bw[((size_t)e * DOUT + o) * 16 + r]);
    } else {
        int j = idx - DOUT * KLORA;
        if (j < DIN * KLORA) {
            int d = j & 4095, er = j >> 12;
            At[(size_t)d * KLORA + er] = __float2half_rn(A[(size_t)er * DIN + d]);
        }
    }
}

// ======================================================================
// host side
// ======================================================================
typedef CUresult (*PFN_encodeTiled)(
    CUtensorMap*, CUtensorMapDataType, cuuint32_t, void*,
    const cuuint64_t*, const cuuint64_t*, const cuuint32_t*, const cuuint32_t*,
    CUtensorMapInterleave, CUtensorMapSwizzle, CUtensorMapL2promotion,
    CUtensorMapFloatOOBfill);

static void make_map(PFN_encodeTiled enc, CUtensorMap* m, void* base,
                     unsigned long long kdim, unsigned long long rows,
                     unsigned boxrows) {
    cuuint64_t dims[2]    = {kdim, rows};
    cuuint64_t strides[1] = {kdim * 2};               // fp16
    cuuint32_t box[2]     = {(cuuint32_t)BK, boxrows};
    cuuint32_t es[2]      = {1u, 1u};
    enc(m, CU_TENSOR_MAP_DATA_TYPE_FLOAT16, 2, base, dims, strides, box, es,
        CU_TENSOR_MAP_INTERLEAVE_NONE, CU_TENSOR_MAP_SWIZZLE_128B,
        CU_TENSOR_MAP_L2_PROMOTION_L2_128B, CU_TENSOR_MAP_FLOAT_OOB_FILL_NONE);
}

extern "C" void kernel_launch(void* const* d_in, const int* in_sizes, int n_in,
                              void* d_out, int out_size) {
    const float* x     = (const float*)d_in[0];
    const float* W     = (const float*)d_in[1];
    const float* b     = (const float*)d_in[2];
    const float* A     = (const float*)d_in[3];
    const float* Bw    = (const float*)d_in[4];
    const float* probs = (const float*)d_in[5];

    __half *xh, *wh, *cm, *at;
    cudaGetSymbolAddress((void**)&xh, g_xh);
    cudaGetSymbolAddress((void**)&wh, g_wh);
    cudaGetSymbolAddress((void**)&cm, g_cm);
    cudaGetSymbolAddress((void**)&at, g_at);

    void* fp = nullptr;
    cudaDriverEntryPointQueryResult qr;
    cudaGetDriverEntryPointByVersion("cuTensorMapEncodeTiled", &fp, 12000,
                                     cudaEnableDefault, &qr);
    PFN_encodeTiled enc = (PFN_encodeTiled)fp;

    // GEMM2 A-operand maps for each M half; B/W map; GEMM1 maps
    CUtensorMap mapX0, mapX1, mapWh, mapC, mapAt;
    make_map(enc, &mapX0, xh,                       DIN, MHALF, BMX);
    make_map(enc, &mapX1, xh + (size_t)MHALF * DIN, DIN, MHALF, BMX);
    make_map(enc, &mapWh, wh, DIN,   DOUT, BNX);
    make_map(enc, &mapC,  cm, KLORA, DOUT, BMX);
    make_map(enc, &mapAt, at, KLORA, DIN,  BNX);

    cudaFuncSetAttribute(gemm_fp16, cudaFuncAttributeMaxDynamicSharedMemorySize,
                         SMEM_TOTAL);

    // lazily create side stream + events on the first (uncaptured) call;
    // replays reuse them so every call does identical work.
    static bool s_init = false;
    static cudaStream_t s_side = 0;
    static cudaEvent_t s_eF = 0, s_e1 = 0, s_e2 = 0;
    if (!s_init) {
        s_init = true;
        if (cudaStreamCreateWithFlags(&s_side, cudaStreamNonBlocking) != cudaSuccess)
            s_side = 0;
        if (s_side) {
            cudaEventCreateWithFlags(&s_eF, cudaEventDisableTiming);
            cudaEventCreateWithFlags(&s_e1, cudaEventDisableTiming);
            cudaEventCreateWithFlags(&s_e2, cudaEventDisableTiming);
        }
    }

    int n4h = (MHALF * DIN) / 4;           // float4s per M-half of x
    int prepN = (DOUT * KLORA + DIN * KLORA + 255) / 256;
    dim3 gridH(DOUT / BNX, MHALF / BMX);   // 32 x 64 per half

    if (s_side) {
        // fork: convert x in two M-halves on the side stream
        cudaEventRecord(s_eF, 0);
        cudaStreamWaitEvent(s_side, s_eF, 0);
        k_x2h<<<n4h / 256, 256, 0, s_side>>>((const float4*)x, (__half2*)xh, n4h);
        cudaEventRecord(s_e1, s_side);
        k_x2h<<<n4h / 256, 256, 0, s_side>>>(
            (const float4*)(x + (size_t)MHALF * DIN),
            (__half2*)(xh + (size_t)MHALF * DIN), n4h);
        cudaEventRecord(s_e2, s_side);

        // main: LoRA prep + W_eff GEMM
        k_prep<<<prepN, 256>>>(Bw, probs, A, cm, at);
        gemm_fp16<<<dim3(DIN / BNX, DOUT / BMX), NTHREADS, SMEM_TOTAL>>>(
            mapC, mapAt, wh, W, nullptr, KLORA / BK, DIN, 1);

        // out halves, each gated only on its own x half
        cudaStreamWaitEvent(0, s_e1, 0);
        gemm_fp16<<<gridH, NTHREADS, SMEM_TOTAL>>>(
            mapX0, mapWh, d_out, nullptr, b, DIN / BK, DOUT, 0);
        cudaStreamWaitEvent(0, s_e2, 0);
        gemm_fp16<<<gridH, NTHREADS, SMEM_TOTAL>>>(
            mapX1, mapWh, (float*)d_out + (size_t)MHALF * DOUT,
            nullptr, b, DIN / BK, DOUT, 0);
    } else {
        k_x2h<<<n4h / 256, 256>>>((const float4*)x, (__half2*)xh, n4h);
        k_x2h<<<n4h / 256, 256>>>(
            (const float4*)(x + (size_t)MHALF * DIN),
            (__half2*)(xh + (size_t)MHALF * DIN), n4h);
        k_prep<<<prepN, 256>>>(Bw, probs, A, cm, at);
        gemm_fp16<<<dim3(DIN / BNX, DOUT / BMX), NTHREADS, SMEM_TOTAL>>>(
            mapC, mapAt, wh, W, nullptr, KLORA / BK, DIN, 1);
        gemm_fp16<<<gridH, NTHREADS, SMEM_TOTAL>>>(
            mapX0, mapWh, d_out, nullptr, b, DIN / BK, DOUT, 0);
        gemm_fp16<<<gridH, NTHREADS, SMEM_TOTAL>>>(
            mapX1, mapWh, (float*)d_out + (size_t)MHALF * DOUT,
            nullptr, b, DIN / BK, DOUT, 0);
    }
}

// round 11
// speedup vs baseline: 1.0521x; 1.0372x over previous
#include <cuda_runtime.h>
#include <cuda.h>
#include <cuda_fp16.h>
#include <cstdint>
#include <cstddef>

// ---------------- problem dims ----------------
#define DIN   4096
#define DOUT  4096
#define MTOT  16384            // B_SZ * S
#define KLORA 256              // E * R

#define BK 64                  // 64 fp16 = 128B row = SW128 atom
#define BNX 128
#define NSTG 3
#define SMEM_CTRL 1024

// GEMM2: BM=128 (8 compute warps + producer, 288 thr), 2 CTAs/SM
// GEMM1: BM=64  (4 compute warps + producer, 160 thr), 2 CTAs/SM
#define SMEM_G2 (SMEM_CTRL + NSTG * (128 + BNX) * BK * 2)   // 99328
#define SMEM_G1 (SMEM_CTRL + NSTG * (64  + BNX) * BK * 2)   // 74752

// ---------------- scratch (device globals; no allocation allowed) ----------
__device__ __align__(256) __half g_xh[(size_t)MTOT * DIN];   // 128 MB fp16 x
__device__ __align__(256) __half g_wh[(size_t)DOUT * DIN];   //  32 MB fp16 W_eff
__device__ __align__(256) __half g_cm[(size_t)DOUT * KLORA]; //   2 MB probs*B
__device__ __align__(256) __half g_at[(size_t)DIN * KLORA];  //   2 MB A^T

// ---------------- PTX helpers ----------------
__device__ __forceinline__ uint32_t smem_u32(const void* p) {
    uint32_t a;
    asm("{ .reg .u64 t; cvta.to.shared.u64 t, %1; cvt.u32.u64 %0, t; }"
        : "=r"(a) : "l"(p));
    return a;
}

#define MBARRIER_INIT(addr, cnt) \
    asm volatile("mbarrier.init.shared.b64 [%0], %1;" \
                 :: "r"((uint32_t)(addr)), "r"((uint32_t)(cnt)) : "memory")

#define MBARRIER_EXPECT_TX(addr, bytes) \
    asm volatile("mbarrier.arrive.expect_tx.shared.b64 _, [%0], %1;" \
                 :: "r"((uint32_t)(addr)), "r"((uint32_t)(bytes)) : "memory")

#define MBARRIER_ARRIVE(addr) \
    asm volatile("mbarrier.arrive.shared.b64 _, [%0];" \
                 :: "r"((uint32_t)(addr)) : "memory")

#define MBARRIER_WAIT_PARITY(addr, parity) do { \
    uint32_t _mb = (uint32_t)(addr); \
    uint32_t _pa = (uint32_t)(parity); \
    asm volatile( \
        "{\n\t.reg .pred P1;\n\t" \
        "WL_%=:\n\t" \
        "mbarrier.try_wait.parity.shared.b64 P1, [%0], %1;\n\t" \
        "@P1 bra.uni WD_%=;\n\t" \
        "bra.uni WL_%=;\n\t" \
        "WD_%=:\n\t}" \
        :: "r"(_mb), "r"(_pa) : "memory"); \
} while (0)

#define TMA2D(sa, pmap, cx, cy, mb) \
    asm volatile("cp.async.bulk.tensor.2d.shared::cta.global.tile.mbarrier::complete_tx::bytes " \
                 "[%0], [%1, {%2, %3}], [%4];" \
                 :: "r"((uint32_t)(sa)), "l"(pmap), "r"((int)(cx)), "r"((int)(cy)), \
                    "r"((uint32_t)(mb)) : "memory")

__device__ __forceinline__ void ldsm4(uint32_t* r, uint32_t a) {
    asm volatile("ldmatrix.sync.aligned.m8n8.x4.shared.b16 {%0,%1,%2,%3}, [%4];"
                 : "=r"(r[0]), "=r"(r[1]), "=r"(r[2]), "=r"(r[3]) : "r"(a));
}

__device__ __forceinline__ void mma16816(float* c, const uint32_t* a,
                                         uint32_t b0, uint32_t b1) {
    asm volatile("mma.sync.aligned.m16n8k16.row.col.f32.f16.f16.f32 "
                 "{%0,%1,%2,%3}, {%4,%5,%6,%7}, {%8,%9}, {%0,%1,%2,%3};"
                 : "+f"(c[0]), "+f"(c[1]), "+f"(c[2]), "+f"(c[3])
                 : "r"(a[0]), "r"(a[1]), "r"(a[2]), "r"(a[3]), "r"(b0), "r"(b1));
}

#define BAR_FULL(s)  (sb + 16 + (uint32_t)(s) * 16)
#define BAR_EMPTY(s) (sb + 24 + (uint32_t)(s) * 16)

// ======================================================================
// Templated GEMM: out[M][N] = Aop[M][K] @ Bop[N][K]^T, fp16 ops / fp32 acc.
//   + addM[M][N] (if non-null) else + bias[N];  outHalf selects output type.
// BMt x 128 CTA tile: (BMt/64) x 4 compute warps of 64x32 + 1 TMA producer.
// 3-stage TMA pipeline; 2 CTAs co-resident per SM. grid: (N/128, M/BMt).
// ======================================================================
template <int BMt>
__global__ __launch_bounds__((BMt / 64) * 128 + 32, 2) void gemm_fp16(
    const __grid_constant__ CUtensorMap tmA,
    const __grid_constant__ CUtensorMap tmB,
    void* __restrict__ outp,
    const float* __restrict__ addM,
    const float* __restrict__ bias,
    int kstages, int ncols, int outHalf)
{
    constexpr int WR   = BMt / 64;
    constexpr int NCW  = WR * 4;
    constexpr int ABYT = BMt * BK * 2;
    constexpr int STGB = (BMt + BNX) * BK * 2;

    extern __shared__ char smem[];
    uint32_t sb = smem_u32(smem);
    int tid = threadIdx.x, wid = tid >> 5, lane = tid & 31;

    if (tid == 0) {
        #pragma unroll
        for (int s = 0; s < NSTG; s++) {
            MBARRIER_INIT(BAR_FULL(s), 1);
            MBARRIER_INIT(BAR_EMPTY(s), NCW);
        }
    }
    __syncthreads();

    if (wid == NCW) {
        // ---------------- TMA producer (lane 0 only) ----------------
        if (lane == 0) {
            const CUtensorMap* pA = &tmA;
            const CUtensorMap* pB = &tmB;
            int st = 0, ph = 1;
            int my = blockIdx.y * BMt, nx = blockIdx.x * BNX;
            for (int s = 0; s < kstages; s++) {
                MBARRIER_WAIT_PARITY(BAR_EMPTY(st), ph);
                MBARRIER_EXPECT_TX(BAR_FULL(st), STGB);
                uint32_t ab = sb + SMEM_CTRL + st * STGB;
                TMA2D(ab,        pA, s * BK, my, BAR_FULL(st));
                TMA2D(ab + ABYT, pB, s * BK, nx, BAR_FULL(st));
                if (++st == NSTG) { st = 0; ph ^= 1; }
            }
        }
        return;
    }

    // ------- compute warps: WR(M) x 4(N) grid of 64(M) x 32(N) tiles ------
    int wr = wid % WR;          // M offset 64*wr
    int wc = wid / WR;          // N offset 32*wc   (0..3)
    int r15 = lane & 15, kh = lane >> 4;

    // per-lane ldmatrix row offsets + SW128 XOR terms (row bits only;
    // k-offset bits [4:6] never reach the swizzle field)
    uint32_t aPre[4], aX[4], bPre[2], bX[2];
    #pragma unroll
    for (int t = 0; t < 4; t++) {
        uint32_t arow = (uint32_t)(64 * wr + 16 * t + r15) * 128u;
        aPre[t] = arow;
        aX[t] = (arow >> 3) & 0x70u;
    }
    #pragma unroll
    for (int t = 0; t < 2; t++) {
        uint32_t brow = (uint32_t)(32 * wc + 16 * t + r15) * 128u;
        bPre[t] = ABYT + brow;
        bX[t] = (brow >> 3) & 0x70u;
    }
    uint32_t khb = (uint32_t)kh << 4;    // 16B per 8-fp16 k-half

    float c[4][4][4];
    #pragma unroll
    for (int mt = 0; mt < 4; mt++)
        #pragma unroll
        for (int nt = 0; nt < 4; nt++)
            #pragma unroll
            for (int e = 0; e < 4; e++) c[mt][nt][e] = 0.0f;

    uint32_t af[2][4][4];      // double-buffered A fragments
    uint32_t bf[2][4];

    int st = 0, ph = 0;
    for (int s = 0; s < kstages; s++) {
        MBARRIER_WAIT_PARITY(BAR_FULL(st), ph);
        uint32_t stbase = sb + SMEM_CTRL + (uint32_t)st * STGB;

        {
            uint32_t kbits = khb;
            #pragma unroll
            for (int mt = 0; mt < 4; mt++)
                ldsm4(af[0][mt], stbase + aPre[mt] + (kbits ^ aX[mt]));
        }
        #pragma unroll
        for (int kk = 0; kk < 4; kk++) {
            int cur = kk & 1;
            uint32_t kbits = ((uint32_t)kk << 5) | khb;
            if (kk < 3) {
                uint32_t kb2 = ((uint32_t)(kk + 1) << 5) | khb;
                #pragma unroll
                for (int mt = 0; mt < 4; mt++)
                    ldsm4(af[cur ^ 1][mt], stbase + aPre[mt] + (kb2 ^ aX[mt]));
            }
            #pragma unroll
            for (int nt = 0; nt < 2; nt++)
                ldsm4(bf[nt], stbase + bPre[nt] + (kbits ^ bX[nt]));
            #pragma unroll
            for (int mt = 0; mt < 4; mt++)
                #pragma unroll
                for (int n8 = 0; n8 < 4; n8++)
                    mma16816(c[mt][n8], af[cur][mt],
                             bf[n8 >> 1][n8 & 1], bf[n8 >> 1][(n8 & 1) + 2]);
        }
        if (lane == 0) MBARRIER_ARRIVE(BAR_EMPTY(st));
        if (++st == NSTG) { st = 0; ph ^= 1; }
    }

    // ---------------- epilogue: direct store from fragments ----------------
    int mbase = blockIdx.y * BMt + 64 * wr;
    int nbase = blockIdx.x * BNX + 32 * wc;
    int frow = lane >> 2, fcol = (lane & 3) * 2;

    #pragma unroll
    for (int mt = 0; mt < 4; mt++) {
        int r0 = mbase + 16 * mt + frow;
        #pragma unroll
        for (int n8 = 0; n8 < 4; n8++) {
            int gc = nbase + 8 * n8 + fcol;
            float add0a, add1a, add0b, add1b;
            if (addM) {
                const float2 wa = *reinterpret_cast<const float2*>(
                    &addM[(size_t)r0 * ncols + gc]);
                const float2 wb = *reinterpret_cast<const float2*>(
                    &addM[(size_t)(r0 + 8) * ncols + gc]);
                add0a = wa.x; add1a = wa.y; add0b = wb.x; add1b = wb.y;
            } else {
                const float2 bb = *reinterpret_cast<const float2*>(&bias[gc]);
                add0a = bb.x; add1a = bb.y; add0b = bb.x; add1b = bb.y;
            }
            float v0 = c[mt][n8][0] + add0a;
            float v1 = c[mt][n8][1] + add1a;
            float v2 = c[mt][n8][2] + add0b;
            float v3 = c[mt][n8][3] + add1b;
            if (outHalf) {
                __half2* oh = (__half2*)outp;
                oh[((size_t)r0 * ncols + gc) >> 1]       = __floats2half2_rn(v0, v1);
                oh[((size_t)(r0 + 8) * ncols + gc) >> 1] = __floats2half2_rn(v2, v3);
            } else {
                float* of = (float*)outp;
                *reinterpret_cast<float2*>(&of[(size_t)r0 * ncols + gc]) =
                    make_float2(v0, v1);
                *reinterpret_cast<float2*>(&of[(size_t)(r0 + 8) * ncols + gc]) =
                    make_float2(v2, v3);
            }
        }
    }
}

// ======================================================================
// prep kernels
// ======================================================================
__global__ void k_x2h(const float4* __restrict__ in, __half2* __restrict__ o, int n4) {
    int i = blockIdx.x * blockDim.x + threadIdx.x;
    if (i < n4) {
        float4 v = in[i];
        o[2 * i]     = __floats2half2_rn(v.x, v.y);
        o[2 * i + 1] = __floats2half2_rn(v.z, v.w);
    }
}

// merged: Cm[o][er] = h(probs[e]*B[e][o][r]);  At[d][er] = h(A[er][d])
__global__ void k_prep(const float* __restrict__ Bw, const float* __restrict__ probs,
                       const float* __restrict__ A,
                       __half* __restrict__ Cm, __half* __restrict__ At) {
    int idx = blockIdx.x * blockDim.x + threadIdx.x;
    if (idx < DOUT * KLORA) {
        int er = idx & 255, o = idx >> 8;
        int e = er >> 4, r = er & 15;
        Cm[idx] = __float2half_rn(probs[e] * Bw[((size_t)e * DOUT + o) * 16 + r]);
    } else {
        int j = idx - DOUT * KLORA;
        if (j < DIN * KLORA) {
            int d = j & 4095, er = j >> 12;
            At[(size_t)d * KLORA + er] = __float2half_rn(A[(size_t)er * DIN + d]);
        }
    }
}

// ======================================================================
// host side
// ======================================================================
typedef CUresult (*PFN_encodeTiled)(
    CUtensorMap*, CUtensorMapDataType, cuuint32_t, void*,
    const cuuint64_t*, const cuuint64_t*, const cuuint32_t*, const cuuint32_t*,
    CUtensorMapInterleave, CUtensorMapSwizzle, CUtensorMapL2promotion,
    CUtensorMapFloatOOBfill);

static void make_map(PFN_encodeTiled enc, CUtensorMap* m, void* base,
                     unsigned long long kdim, unsigned long long rows,
                     unsigned boxrows) {
    cuuint64_t dims[2]    = {kdim, rows};
    cuuint64_t strides[1] = {kdim * 2};               // fp16
    cuuint32_t box[2]     = {(cuuint32_t)BK, boxrows};
    cuuint32_t es[2]      = {1u, 1u};
    enc(m, CU_TENSOR_MAP_DATA_TYPE_FLOAT16, 2, base, dims, strides, box, es,
        CU_TENSOR_MAP_INTERLEAVE_NONE, CU_TENSOR_MAP_SWIZZLE_128B,
        CU_TENSOR_MAP_L2_PROMOTION_L2_128B, CU_TENSOR_MAP_FLOAT_OOB_FILL_NONE);
}

extern "C" void kernel_launch(void* const* d_in, const int* in_sizes, int n_in,
                              void* d_out, int out_size) {
    const float* x     = (const float*)d_in[0];
    const float* W     = (const float*)d_in[1];
    const float* b     = (const float*)d_in[2];
    const float* A     = (const float*)d_in[3];
    const float* Bw    = (const float*)d_in[4];
    const float* probs = (const float*)d_in[5];

    __half *xh, *wh, *cm, *at;
    cudaGetSymbolAddress((void**)&xh, g_xh);
    cudaGetSymbolAddress((void**)&wh, g_wh);
    cudaGetSymbolAddress((void**)&cm, g_cm);
    cudaGetSymbolAddress((void**)&at, g_at);

    void* fp = nullptr;
    cudaDriverEntryPointQueryResult qr;
    cudaGetDriverEntryPointByVersion("cuTensorMapEncodeTiled", &fp, 12000,
                                     cudaEnableDefault, &qr);
    PFN_encodeTiled enc = (PFN_encodeTiled)fp;

    CUtensorMap mapX, mapWh, mapC, mapAt;
    make_map(enc, &mapX,  xh, DIN,   MTOT, 128);   // A of GEMM2 (BM=128)
    make_map(enc, &mapWh, wh, DIN,   DOUT, BNX);   // B of GEMM2
    make_map(enc, &mapC,  cm, KLORA, DOUT, 64);    // A of GEMM1 (BM=64)
    make_map(enc, &mapAt, at, KLORA, DIN,  BNX);   // B of GEMM1

    auto* g2 = gemm_fp16<128>;
    auto* g1 = gemm_fp16<64>;
    cudaFuncSetAttribute(g2, cudaFuncAttributeMaxDynamicSharedMemorySize, SMEM_G2);
    cudaFuncSetAttribute(g1, cudaFuncAttributeMaxDynamicSharedMemorySize, SMEM_G1);

    // lazily create side stream + fork/join events on the first (uncaptured)
    // call; replays reuse them so every call does identical work.
    static bool s_init = false;
    static cudaStream_t s_side = 0;
    static cudaEvent_t s_eF = 0, s_eJ = 0;
    if (!s_init) {
        s_init = true;
        if (cudaStreamCreateWithFlags(&s_side, cudaStreamNonBlocking) != cudaSuccess)
            s_side = 0;
        if (s_side) {
            cudaEventCreateWithFlags(&s_eF, cudaEventDisableTiming);
            cudaEventCreateWithFlags(&s_eJ, cudaEventDisableTiming);
        }
    }

    int n4 = (MTOT * DIN) / 4;
    int prepN = (DOUT * KLORA + DIN * KLORA + 255) / 256;
    dim3 grid1(DIN / BNX, DOUT / 64);    // 32 x 64
    dim3 grid2(DOUT / BNX, MTOT / 128);  // 32 x 128

    if (s_side) {
        // fork: x -> fp16 on side stream; LoRA prep + W_eff GEMM on main
        cudaEventRecord(s_eF, 0);
        cudaStreamWaitEvent(s_side, s_eF, 0);
        k_x2h<<<n4 / 256, 256, 0, s_side>>>((const float4*)x, (__half2*)xh, n4);
        cudaEventRecord(s_eJ, s_side);

        k_prep<<<prepN, 256>>>(Bw, probs, A, cm, at);
        g1<<<grid1, 160, SMEM_G1>>>(mapC, mapAt, wh, W, nullptr,
                                    KLORA / BK, DIN, 1);

        cudaStreamWaitEvent(0, s_eJ, 0);   // join before the big GEMM
    } else {
        k_x2h<<<n4 / 256, 256>>>((const float4*)x, (__half2*)xh, n4);
        k_prep<<<prepN, 256>>>(Bw, probs, A, cm, at);
        g1<<<grid1, 160, SMEM_G1>>>(mapC, mapAt, wh, W, nullptr,
                                    KLORA / BK, DIN, 1);
    }

    // out = xh @ W_eff^T + b   [M=16384, N=4096, K=4096]
    g2<<<grid2, 288, SMEM_G2>>>(mapX, mapWh, d_out, nullptr, b,
                                DIN / BK, DOUT, 0);
}

// round 12
// speedup vs baseline: 1.0533x; 1.0012x over previous
#include <cuda_runtime.h>
#include <cuda.h>
#include <cuda_fp16.h>
#include <cstdint>
#include <cstddef>

// ---------------- problem dims ----------------
#define DIN   4096
#define DOUT  4096
#define MTOT  16384            // B_SZ * S
#define KLORA 256              // E * R

#define BK 64                  // 64 fp16 = 128B row = SW128 atom
#define BNX 128
#define NSTG 3
#define SMEM_CTRL 1024

// GEMM2: BM=128 (8 compute warps + producer, 288 thr), 2 CTAs/SM
// GEMM1: BM=64  (4 compute warps + producer, 160 thr), 2 CTAs/SM
#define SMEM_G2 (SMEM_CTRL + NSTG * (128 + BNX) * BK * 2)   // 99328
#define SMEM_G1 (SMEM_CTRL + NSTG * (64  + BNX) * BK * 2)   // 74752

#define NXCHUNK 128            // 128-row chunks of x
#define CTAS_PER_CHUNK 512     // x2h CTAs per chunk (128*4096/4 f4 / 256)

// ---------------- scratch (device globals; no allocation allowed) ----------
__device__ __align__(256) __half g_xh[(size_t)MTOT * DIN];   // 128 MB fp16 x
__device__ __align__(256) __half g_wh[(size_t)DOUT * DIN];   //  32 MB fp16 W_eff
__device__ __align__(256) __half g_cm[(size_t)DOUT * KLORA]; //   2 MB probs*B
__device__ __align__(256) __half g_at[(size_t)DIN * KLORA];  //   2 MB A^T
__device__ int g_xdone[NXCHUNK];                             // x2h progress

// ---------------- PTX helpers ----------------
__device__ __forceinline__ uint32_t smem_u32(const void* p) {
    uint32_t a;
    asm("{ .reg .u64 t; cvta.to.shared.u64 t, %1; cvt.u32.u64 %0, t; }"
        : "=r"(a) : "l"(p));
    return a;
}

#define MBARRIER_INIT(addr, cnt) \
    asm volatile("mbarrier.init.shared.b64 [%0], %1;" \
                 :: "r"((uint32_t)(addr)), "r"((uint32_t)(cnt)) : "memory")

#define MBARRIER_EXPECT_TX(addr, bytes) \
    asm volatile("mbarrier.arrive.expect_tx.shared.b64 _, [%0], %1;" \
                 :: "r"((uint32_t)(addr)), "r"((uint32_t)(bytes)) : "memory")

#define MBARRIER_ARRIVE(addr) \
    asm volatile("mbarrier.arrive.shared.b64 _, [%0];" \
                 :: "r"((uint32_t)(addr)) : "memory")

#define MBARRIER_WAIT_PARITY(addr, parity) do { \
    uint32_t _mb = (uint32_t)(addr); \
    uint32_t _pa = (uint32_t)(parity); \
    asm volatile( \
        "{\n\t.reg .pred P1;\n\t" \
        "WL_%=:\n\t" \
        "mbarrier.try_wait.parity.shared.b64 P1, [%0], %1;\n\t" \
        "@P1 bra.uni WD_%=;\n\t" \
        "bra.uni WL_%=;\n\t" \
        "WD_%=:\n\t}" \
        :: "r"(_mb), "r"(_pa) : "memory"); \
} while (0)

#define TMA2D(sa, pmap, cx, cy, mb) \
    asm volatile("cp.async.bulk.tensor.2d.shared::cta.global.tile.mbarrier::complete_tx::bytes " \
                 "[%0], [%1, {%2, %3}], [%4];" \
                 :: "r"((uint32_t)(sa)), "l"(pmap), "r"((int)(cx)), "r"((int)(cy)), \
                    "r"((uint32_t)(mb)) : "memory")

__device__ __forceinline__ void ldsm4(uint32_t* r, uint32_t a) {
    asm volatile("ldmatrix.sync.aligned.m8n8.x4.shared.b16 {%0,%1,%2,%3}, [%4];"
                 : "=r"(r[0]), "=r"(r[1]), "=r"(r[2]), "=r"(r[3]) : "r"(a));
}

__device__ __forceinline__ void mma16816(float* c, const uint32_t* a,
                                         uint32_t b0, uint32_t b1) {
    asm volatile("mma.sync.aligned.m16n8k16.row.col.f32.f16.f16.f32 "
                 "{%0,%1,%2,%3}, {%4,%5,%6,%7}, {%8,%9}, {%0,%1,%2,%3};"
                 : "+f"(c[0]), "+f"(c[1]), "+f"(c[2]), "+f"(c[3])
                 : "r"(a[0]), "r"(a[1]), "r"(a[2]), "r"(a[3]), "r"(b0), "r"(b1));
}

#define BAR_FULL(s)  (sb + 16 + (uint32_t)(s) * 16)
#define BAR_EMPTY(s) (sb + 24 + (uint32_t)(s) * 16)

// ======================================================================
// Templated GEMM: out[M][N] = Aop[M][K] @ Bop[N][K]^T, fp16 ops / fp32 acc.
//   + addM[M][N] (if non-null) else + bias[N];  outHalf selects output type.
//   xwait: producer spin-waits for x-chunk blockIdx.y conversion (GEMM2).
// BMt x 128 CTA tile: (BMt/64) x 4 compute warps of 64x32 + 1 TMA producer.
// 3-stage TMA pipeline; 2 CTAs co-resident per SM. grid: (N/128, M/BMt).
// ======================================================================
template <int BMt>
__global__ __launch_bounds__((BMt / 64) * 128 + 32, 2) void gemm_fp16(
    const __grid_constant__ CUtensorMap tmA,
    const __grid_constant__ CUtensorMap tmB,
    void* __restrict__ outp,
    const float* __restrict__ addM,
    const float* __restrict__ bias,
    int kstages, int ncols, int outHalf, int xwait)
{
    constexpr int WR   = BMt / 64;
    constexpr int NCW  = WR * 4;
    constexpr int ABYT = BMt * BK * 2;
    constexpr int STGB = (BMt + BNX) * BK * 2;

    extern __shared__ char smem[];
    uint32_t sb = smem_u32(smem);
    int tid = threadIdx.x, wid = tid >> 5, lane = tid & 31;

    if (tid == 0) {
        #pragma unroll
        for (int s = 0; s < NSTG; s++) {
            MBARRIER_INIT(BAR_FULL(s), 1);
            MBARRIER_INIT(BAR_EMPTY(s), NCW);
        }
    }
    __syncthreads();

    if (wid == NCW) {
        // ---------------- TMA producer (lane 0 only) ----------------
        if (lane == 0) {
            if (xwait) {
                // wait until this CTA's 128 x-rows are converted
                volatile int* vc = &g_xdone[blockIdx.y];
                while (*vc < CTAS_PER_CHUNK) __nanosleep(128);
                __threadfence();
            }
            const CUtensorMap* pA = &tmA;
            const CUtensorMap* pB = &tmB;
            int st = 0, ph = 1;
            int my = blockIdx.y * BMt, nx = blockIdx.x * BNX;
            for (int s = 0; s < kstages; s++) {
                MBARRIER_WAIT_PARITY(BAR_EMPTY(st), ph);
                MBARRIER_EXPECT_TX(BAR_FULL(st), STGB);
                uint32_t ab = sb + SMEM_CTRL + st * STGB;
                TMA2D(ab,        pA, s * BK, my, BAR_FULL(st));
                TMA2D(ab + ABYT, pB, s * BK, nx, BAR_FULL(st));
                if (++st == NSTG) { st = 0; ph ^= 1; }
            }
        }
        return;
    }

    // ------- compute warps: WR(M) x 4(N) grid of 64(M) x 32(N) tiles ------
    int wr = wid % WR;          // M offset 64*wr
    int wc = wid / WR;          // N offset 32*wc   (0..3)
    int r15 = lane & 15, kh = lane >> 4;

    // per-lane ldmatrix row offsets + SW128 XOR terms (row bits only;
    // k-offset bits [4:6] never reach the swizzle field)
    uint32_t aPre[4], aX[4], bPre[2], bX[2];
    #pragma unroll
    for (int t = 0; t < 4; t++) {
        uint32_t arow = (uint32_t)(64 * wr + 16 * t + r15) * 128u;
        aPre[t] = arow;
        aX[t] = (arow >> 3) & 0x70u;
    }
    #pragma unroll
    for (int t = 0; t < 2; t++) {
        uint32_t brow = (uint32_t)(32 * wc + 16 * t + r15) * 128u;
        bPre[t] = ABYT + brow;
        bX[t] = (brow >> 3) & 0x70u;
    }
    uint32_t khb = (uint32_t)kh << 4;    // 16B per 8-fp16 k-half

    float c[4][4][4];
    #pragma unroll
    for (int mt = 0; mt < 4; mt++)
        #pragma unroll
        for (int nt = 0; nt < 4; nt++)
            #pragma unroll
            for (int e = 0; e < 4; e++) c[mt][nt][e] = 0.0f;

    uint32_t af[2][4][4];      // double-buffered A fragments
    uint32_t bf[2][4];

    int st = 0, ph = 0;
    for (int s = 0; s < kstages; s++) {
        MBARRIER_WAIT_PARITY(BAR_FULL(st), ph);
        uint32_t stbase = sb + SMEM_CTRL + (uint32_t)st * STGB;

        {
            uint32_t kbits = khb;
            #pragma unroll
            for (int mt = 0; mt < 4; mt++)
                ldsm4(af[0][mt], stbase + aPre[mt] + (kbits ^ aX[mt]));
        }
        #pragma unroll
        for (int kk = 0; kk < 4; kk++) {
            int cur = kk & 1;
            uint32_t kbits = ((uint32_t)kk << 5) | khb;
            if (kk < 3) {
                uint32_t kb2 = ((uint32_t)(kk + 1) << 5) | khb;
                #pragma unroll
                for (int mt = 0; mt < 4; mt++)
                    ldsm4(af[cur ^ 1][mt], stbase + aPre[mt] + (kb2 ^ aX[mt]));
            }
            #pragma unroll
            for (int nt = 0; nt < 2; nt++)
                ldsm4(bf[nt], stbase + bPre[nt] + (kbits ^ bX[nt]));
            #pragma unroll
            for (int mt = 0; mt < 4; mt++)
                #pragma unroll
                for (int n8 = 0; n8 < 4; n8++)
                    mma16816(c[mt][n8], af[cur][mt],
                             bf[n8 >> 1][n8 & 1], bf[n8 >> 1][(n8 & 1) + 2]);
        }
        if (lane == 0) MBARRIER_ARRIVE(BAR_EMPTY(st));
        if (++st == NSTG) { st = 0; ph ^= 1; }
    }

    // ---------------- epilogue: direct store from fragments ----------------
    int mbase = blockIdx.y * BMt + 64 * wr;
    int nbase = blockIdx.x * BNX + 32 * wc;
    int frow = lane >> 2, fcol = (lane & 3) * 2;

    #pragma unroll
    for (int mt = 0; mt < 4; mt++) {
        int r0 = mbase + 16 * mt + frow;
        #pragma unroll
        for (int n8 = 0; n8 < 4; n8++) {
            int gc = nbase + 8 * n8 + fcol;
            float add0a, add1a, add0b, add1b;
            if (addM) {
                const float2 wa = *reinterpret_cast<const float2*>(
                    &addM[(size_t)r0 * ncols + gc]);
                const float2 wb = *reinterpret_cast<const float2*>(
                    &addM[(size_t)(r0 + 8) * ncols + gc]);
                add0a = wa.x; add1a = wa.y; add0b = wb.x; add1b = wb.y;
            } else {
                const float2 bb = *reinterpret_cast<const float2*>(&bias[gc]);
                add0a = bb.x; add1a = bb.y; add0b = bb.x; add1b = bb.y;
            }
            float v0 = c[mt][n8][0] + add0a;
            float v1 = c[mt][n8][1] + add1a;
            float v2 = c[mt][n8][2] + add0b;
            float v3 = c[mt][n8][3] + add1b;
            if (outHalf) {
                __half2* oh = (__half2*)outp;
                oh[((size_t)r0 * ncols + gc) >> 1]       = __floats2half2_rn(v0, v1);
                oh[((size_t)(r0 + 8) * ncols + gc) >> 1] = __floats2half2_rn(v2, v3);
            } else {
                float* of = (float*)outp;
                *reinterpret_cast<float2*>(&of[(size_t)r0 * ncols + gc]) =
                    make_float2(v0, v1);
                *reinterpret_cast<float2*>(&of[(size_t)(r0 + 8) * ncols + gc]) =
                    make_float2(v2, v3);
            }
        }
    }
}

// ======================================================================
// prep kernels
// ======================================================================
__global__ void k_reset() {
    if (threadIdx.x < NXCHUNK) g_xdone[threadIdx.x] = 0;
}

// x -> fp16, with per-128-row-chunk completion counting.
// One CTA = 256 float4 = 1024 floats (1/4 of a 4096-wide row) -> one chunk.
__global__ void k_x2h(const float4* __restrict__ in, __half2* __restrict__ o, int n4) {
    int i = blockIdx.x * blockDim.x + threadIdx.x;
    if (i < n4) {
        float4 v = in[i];
        o[2 * i]     = __floats2half2_rn(v.x, v.y);
        o[2 * i + 1] = __floats2half2_rn(v.z, v.w);
    }
    __syncthreads();
    if (threadIdx.x == 0) {
        __threadfence();
        atomicAdd(&g_xdone[blockIdx.x >> 9], 1);   // 512 CTAs per chunk
    }
}

// merged: Cm[o][er] = h(probs[e]*B[e][o][r]);  At[d][er] = h(A[er][d])
__global__ void k_prep(const float* __restrict__ Bw, const float* __restrict__ probs,
                       const float* __restrict__ A,
                       __half* __restrict__ Cm, __half* __restrict__ At) {
    int idx = blockIdx.x * blockDim.x + threadIdx.x;
    if (idx < DOUT * KLORA) {
        int er = idx & 255, o = idx >> 8;
        int e = er >> 4, r = er & 15;
        Cm[idx] = __float2half_rn(probs[e] * Bw[((size_t)e * DOUT + o) * 16 + r]);
    } else {
        int j = idx - DOUT * KLORA;
        if (j < DIN * KLORA) {
            int d = j & 4095, er = j >> 12;
            At[(size_t)d * KLORA + er] = __float2half_rn(A[(size_t)er * DIN + d]);
        }
    }
}

// ======================================================================
// host side
// ======================================================================
typedef CUresult (*PFN_encodeTiled)(
    CUtensorMap*, CUtensorMapDataType, cuuint32_t, void*,
    const cuuint64_t*, const cuuint64_t*, const cuuint32_t*, const cuuint32_t*,
    CUtensorMapInterleave, CUtensorMapSwizzle, CUtensorMapL2promotion,
    CUtensorMapFloatOOBfill);

static void make_map(PFN_encodeTiled enc, CUtensorMap* m, void* base,
                     unsigned long long kdim, unsigned long long rows,
                     unsigned boxrows) {
    cuuint64_t dims[2]    = {kdim, rows};
    cuuint64_t strides[1] = {kdim * 2};               // fp16
    cuuint32_t box[2]     = {(cuuint32_t)BK, boxrows};
    cuuint32_t es[2]      = {1u, 1u};
    enc(m, CU_TENSOR_MAP_DATA_TYPE_FLOAT16, 2, base, dims, strides, box, es,
        CU_TENSOR_MAP_INTERLEAVE_NONE, CU_TENSOR_MAP_SWIZZLE_128B,
        CU_TENSOR_MAP_L2_PROMOTION_L2_128B, CU_TENSOR_MAP_FLOAT_OOB_FILL_NONE);
}

extern "C" void kernel_launch(void* const* d_in, const int* in_sizes, int n_in,
                              void* d_out, int out_size) {
    const float* x     = (const float*)d_in[0];
    const float* W     = (const float*)d_in[1];
    const float* b     = (const float*)d_in[2];
    const float* A     = (const float*)d_in[3];
    const float* Bw    = (const float*)d_in[4];
    const float* probs = (const float*)d_in[5];

    __half *xh, *wh, *cm, *at;
    cudaGetSymbolAddress((void**)&xh, g_xh);
    cudaGetSymbolAddress((void**)&wh, g_wh);
    cudaGetSymbolAddress((void**)&cm, g_cm);
    cudaGetSymbolAddress((void**)&at, g_at);

    void* fp = nullptr;
    cudaDriverEntryPointQueryResult qr;
    cudaGetDriverEntryPointByVersion("cuTensorMapEncodeTiled", &fp, 12000,
                                     cudaEnableDefault, &qr);
    PFN_encodeTiled enc = (PFN_encodeTiled)fp;

    CUtensorMap mapX, mapWh, mapC, mapAt;
    make_map(enc, &mapX,  xh, DIN,   MTOT, 128);   // A of GEMM2 (BM=128)
    make_map(enc, &mapWh, wh, DIN,   DOUT, BNX);   // B of GEMM2
    make_map(enc, &mapC,  cm, KLORA, DOUT, 64);    // A of GEMM1 (BM=64)
    make_map(enc, &mapAt, at, KLORA, DIN,  BNX);   // B of GEMM1

    auto* g2 = gemm_fp16<128>;
    auto* g1 = gemm_fp16<64>;
    cudaFuncSetAttribute(g2, cudaFuncAttributeMaxDynamicSharedMemorySize, SMEM_G2);
    cudaFuncSetAttribute(g1, cudaFuncAttributeMaxDynamicSharedMemorySize, SMEM_G1);

    // lazily create side stream + fork/join events on the first (uncaptured)
    // call; replays reuse them so every call does identical work.
    static bool s_init = false;
    static cudaStream_t s_side = 0;
    static cudaEvent_t s_eF = 0, s_eJ = 0;
    if (!s_init) {
        s_init = true;
        if (cudaStreamCreateWithFlags(&s_side, cudaStreamNonBlocking) != cudaSuccess)
            s_side = 0;
        if (s_side) {
            cudaEventCreateWithFlags(&s_eF, cudaEventDisableTiming);
            cudaEventCreateWithFlags(&s_eJ, cudaEventDisableTiming);
        }
    }

    int n4 = (MTOT * DIN) / 4;
    int prepN = (DOUT * KLORA + DIN * KLORA + 255) / 256;
    dim3 grid1(DIN / BNX, DOUT / 64);    // 32 x 64
    dim3 grid2(DOUT / BNX, MTOT / 128);  // 32 x 128

    if (s_side) {
        // fork: reset progress flags + convert x on side stream
        cudaEventRecord(s_eF, 0);
        cudaStreamWaitEvent(s_side, s_eF, 0);
        k_reset<<<1, NXCHUNK, 0, s_side>>>();
        k_x2h<<<n4 / 256, 256, 0, s_side>>>((const float4*)x, (__half2*)xh, n4);
        cudaEventRecord(s_eJ, s_side);

        // main: LoRA prep + W_eff GEMM, then GEMM2 immediately.
        // GEMM2 producers self-synchronize on per-chunk x progress flags.
        k_prep<<<prepN, 256>>>(Bw, probs, A, cm, at);
        g1<<<grid1, 160, SMEM_G1>>>(mapC, mapAt, wh, W, nullptr,
                                    KLORA / BK, DIN, 1, 0);
        g2<<<grid2, 288, SMEM_G2>>>(mapX, mapWh, d_out, nullptr, b,
                                    DIN / BK, DOUT, 0, 1);
        cudaStreamWaitEvent(0, s_eJ, 0);   // join side stream after GEMM2
    } else {
        k_reset<<<1, NXCHUNK>>>();
        k_x2h<<<n4 / 256, 256>>>((const float4*)x, (__half2*)xh, n4);
        k_prep<<<prepN, 256>>>(Bw, probs, A, cm, at);
        g1<<<grid1, 160, SMEM_G1>>>(mapC, mapAt, wh, W, nullptr,
                                    KLORA / BK, DIN, 1, 0);
        g2<<<grid2, 288, SMEM_G2>>>(mapX, mapWh, d_out, nullptr, b,
                                    DIN / BK, DOUT, 0, 1);
    }
}

// round 13
// speedup vs baseline: 1.0977x; 1.0422x over previous
#include <cuda_runtime.h>
#include <cuda.h>
#include <cuda_fp16.h>
#include <cstdint>
#include <cstddef>

// ---------------- problem dims ----------------
#define DIN   4096
#define DOUT  4096
#define MTOT  16384            // B_SZ * S
#define KLORA 256              // E * R

#define BK 64                  // 64 fp16 = 128B row = SW128 atom
#define BNX 128
#define NSTG 3
#define SMEM_CTRL 1024
#define SMEM_G (SMEM_CTRL + NSTG * (128 + BNX) * BK * 2)   // 99328

#define NXCHUNK 128            // 128-row chunks of x
#define CTAS_PER_CHUNK 512     // x2h CTAs per chunk
#define NSTRIP 32              // 128-col strips of wh (DIN/128)
#define STRIP_ARRIVALS 256     // 32 role-1 CTAs x 8 warps per strip

#define ROLE1N 1024            // W_eff tiles: (DOUT/128) x (DIN/128)
#define ROLE2N 4096            // out tiles:  (DOUT/128) x (MTOT/128)
#define GRIDT  (ROLE1N + ROLE2N)

// ---------------- scratch (device globals; no allocation allowed) ----------
__device__ __align__(256) __half g_xh[(size_t)MTOT * DIN];   // 128 MB fp16 x
__device__ __align__(256) __half g_wh[(size_t)DOUT * DIN];   //  32 MB fp16 W_eff
__device__ __align__(256) __half g_cm[(size_t)DOUT * KLORA]; //   2 MB probs*B
__device__ __align__(256) __half g_at[(size_t)DIN * KLORA];  //   2 MB A^T
__device__ int g_xdone[NXCHUNK];                             // x2h progress
__device__ int g_whdone[NSTRIP];                             // W_eff strip progress

// ---------------- PTX helpers ----------------
__device__ __forceinline__ uint32_t smem_u32(const void* p) {
    uint32_t a;
    asm("{ .reg .u64 t; cvta.to.shared.u64 t, %1; cvt.u32.u64 %0, t; }"
        : "=r"(a) : "l"(p));
    return a;
}

#define MBARRIER_INIT(addr, cnt) \
    asm volatile("mbarrier.init.shared.b64 [%0], %1;" \
                 :: "r"((uint32_t)(addr)), "r"((uint32_t)(cnt)) : "memory")

#define MBARRIER_EXPECT_TX(addr, bytes) \
    asm volatile("mbarrier.arrive.expect_tx.shared.b64 _, [%0], %1;" \
                 :: "r"((uint32_t)(addr)), "r"((uint32_t)(bytes)) : "memory")

#define MBARRIER_ARRIVE(addr) \
    asm volatile("mbarrier.arrive.shared.b64 _, [%0];" \
                 :: "r"((uint32_t)(addr)) : "memory")

#define MBARRIER_WAIT_PARITY(addr, parity) do { \
    uint32_t _mb = (uint32_t)(addr); \
    uint32_t _pa = (uint32_t)(parity); \
    asm volatile( \
        "{\n\t.reg .pred P1;\n\t" \
        "WL_%=:\n\t" \
        "mbarrier.try_wait.parity.shared.b64 P1, [%0], %1;\n\t" \
        "@P1 bra.uni WD_%=;\n\t" \
        "bra.uni WL_%=;\n\t" \
        "WD_%=:\n\t}" \
        :: "r"(_mb), "r"(_pa) : "memory"); \
} while (0)

#define TMA2D(sa, pmap, cx, cy, mb) \
    asm volatile("cp.async.bulk.tensor.2d.shared::cta.global.tile.mbarrier::complete_tx::bytes " \
                 "[%0], [%1, {%2, %3}], [%4];" \
                 :: "r"((uint32_t)(sa)), "l"(pmap), "r"((int)(cx)), "r"((int)(cy)), \
                    "r"((uint32_t)(mb)) : "memory")

__device__ __forceinline__ void ldsm4(uint32_t* r, uint32_t a) {
    asm volatile("ldmatrix.sync.aligned.m8n8.x4.shared.b16 {%0,%1,%2,%3}, [%4];"
                 : "=r"(r[0]), "=r"(r[1]), "=r"(r[2]), "=r"(r[3]) : "r"(a));
}

__device__ __forceinline__ void mma16816(float* c, const uint32_t* a,
                                         uint32_t b0, uint32_t b1) {
    asm volatile("mma.sync.aligned.m16n8k16.row.col.f32.f16.f16.f32 "
                 "{%0,%1,%2,%3}, {%4,%5,%6,%7}, {%8,%9}, {%0,%1,%2,%3};"
                 : "+f"(c[0]), "+f"(c[1]), "+f"(c[2]), "+f"(c[3])
                 : "r"(a[0]), "r"(a[1]), "r"(a[2]), "r"(a[3]), "r"(b0), "r"(b1));
}

#define BAR_FULL(s)  (sb + 16 + (uint32_t)(s) * 16)
#define BAR_EMPTY(s) (sb + 24 + (uint32_t)(s) * 16)

// ======================================================================
// Mega-kernel: role-1 CTAs (blockIdx < 1024) build W_eff = h(Cm@At^T + W)
// and publish per-128-col-strip flags; role-2 CTAs compute
// out = xh @ W_eff^T + b, gating A-TMA on x-chunk flags and each K-stage's
// B-TMA on the corresponding W_eff strip flag. Role-1s are dispatched
// before role-2s (blockIdx order) => no deadlock.
// 128x128 CTA tile: 8 compute warps (2Mx4N of 64x32) + 1 TMA producer.
// ======================================================================
__global__ __launch_bounds__(288, 2) void gemm_mega(
    const __grid_constant__ CUtensorMap tmX,
    const __grid_constant__ CUtensorMap tmWh,
    const __grid_constant__ CUtensorMap tmC,
    const __grid_constant__ CUtensorMap tmAt,
    float* __restrict__ outp,
    const float* __restrict__ W,
    const float* __restrict__ bias,
    __half* __restrict__ wh)
{
    constexpr int ABYT = 128 * BK * 2;          // 16384
    constexpr int STGB = (128 + BNX) * BK * 2;  // 32768

    extern __shared__ char smem[];
    uint32_t sb = smem_u32(smem);
    int tid = threadIdx.x, wid = tid >> 5, lane = tid & 31;

    int c = blockIdx.x;
    bool r1 = (c < ROLE1N);
    int my, nx, kst;
    const CUtensorMap *pA, *pB;
    if (r1) {
        int n1 = c >> 5, m1 = c & 31;
        my = m1 * 128;  nx = n1 * 128;  kst = KLORA / BK;   // 4
        pA = &tmC;  pB = &tmAt;
    } else {
        int c2 = c - ROLE1N;
        my = (c2 >> 5) * 128;  nx = (c2 & 31) * 128;  kst = DIN / BK;  // 64
        pA = &tmX;  pB = &tmWh;
    }

    if (tid == 0) {
        #pragma unroll
        for (int s = 0; s < NSTG; s++) {
            MBARRIER_INIT(BAR_FULL(s), 1);
            MBARRIER_INIT(BAR_EMPTY(s), 8);
        }
    }
    __syncthreads();

    if (wid == 8) {
        // ---------------- TMA producer (lane 0 only) ----------------
        if (lane == 0) {
            if (!r1) {
                volatile int* vx = &g_xdone[my >> 7];
                while (*vx < CTAS_PER_CHUNK) __nanosleep(128);
                __threadfence();
            }
            int jready = 0;
            int st = 0, ph = 1;
            for (int s = 0; s < kst; s++) {
                if (!r1) {
                    int need = s >> 1;           // wh strip for this K-stage
                    if (jready <= need) {
                        volatile int* vw = &g_whdone[need];
                        while (*vw < STRIP_ARRIVALS) __nanosleep(128);
                        __threadfence();
                        jready = need + 1;
                    }
                }
                MBARRIER_WAIT_PARITY(BAR_EMPTY(st), ph);
                MBARRIER_EXPECT_TX(BAR_FULL(st), STGB);
                uint32_t ab = sb + SMEM_CTRL + st * STGB;
                TMA2D(ab,        pA, s * BK, my, BAR_FULL(st));
                TMA2D(ab + ABYT, pB, s * BK, nx, BAR_FULL(st));
                if (++st == NSTG) { st = 0; ph ^= 1; }
            }
        }
        return;
    }

    // ------- compute warps: 2(M) x 4(N) grid of 64(M) x 32(N) tiles -------
    int wr = wid & 1;           // M offset 64*wr
    int wc = wid >> 1;          // N offset 32*wc
    int r15 = lane & 15, kh = lane >> 4;

    uint32_t aPre[4], aX[4], bPre[2], bX[2];
    #pragma unroll
    for (int t = 0; t < 4; t++) {
        uint32_t arow = (uint32_t)(64 * wr + 16 * t + r15) * 128u;
        aPre[t] = arow;
        aX[t] = (arow >> 3) & 0x70u;
    }
    #pragma unroll
    for (int t = 0; t < 2; t++) {
        uint32_t brow = (uint32_t)(32 * wc + 16 * t + r15) * 128u;
        bPre[t] = ABYT + brow;
        bX[t] = (brow >> 3) & 0x70u;
    }
    uint32_t khb = (uint32_t)kh << 4;

    float acc[4][4][4];
    #pragma unroll
    for (int mt = 0; mt < 4; mt++)
        #pragma unroll
        for (int nt = 0; nt < 4; nt++)
            #pragma unroll
            for (int e = 0; e < 4; e++) acc[mt][nt][e] = 0.0f;

    uint32_t af[2][4][4];
    uint32_t bf[2][4];

    int st = 0, ph = 0;
    for (int s = 0; s < kst; s++) {
        MBARRIER_WAIT_PARITY(BAR_FULL(st), ph);
        uint32_t stbase = sb + SMEM_CTRL + (uint32_t)st * STGB;

        {
            uint32_t kbits = khb;
            #pragma unroll
            for (int mt = 0; mt < 4; mt++)
                ldsm4(af[0][mt], stbase + aPre[mt] + (kbits ^ aX[mt]));
        }
        #pragma unroll
        for (int kk = 0; kk < 4; kk++) {
            int cur = kk & 1;
            uint32_t kbits = ((uint32_t)kk << 5) | khb;
            if (kk < 3) {
                uint32_t kb2 = ((uint32_t)(kk + 1) << 5) | khb;
                #pragma unroll
                for (int mt = 0; mt < 4; mt++)
                    ldsm4(af[cur ^ 1][mt], stbase + aPre[mt] + (kb2 ^ aX[mt]));
            }
            #pragma unroll
            for (int nt = 0; nt < 2; nt++)
                ldsm4(bf[nt], stbase + bPre[nt] + (kbits ^ bX[nt]));
            #pragma unroll
            for (int mt = 0; mt < 4; mt++)
                #pragma unroll
                for (int n8 = 0; n8 < 4; n8++)
                    mma16816(acc[mt][n8], af[cur][mt],
                             bf[n8 >> 1][n8 & 1], bf[n8 >> 1][(n8 & 1) + 2]);
        }
        if (lane == 0) MBARRIER_ARRIVE(BAR_EMPTY(st));
        if (++st == NSTG) { st = 0; ph ^= 1; }
    }

    // ---------------- epilogue ----------------
    int mbase = my + 64 * wr;
    int nbase = nx + 32 * wc;
    int frow = lane >> 2, fcol = (lane & 3) * 2;

    if (r1) {
        // W_eff = h(acc + W); publish strip flag
        #pragma unroll
        for (int mt = 0; mt < 4; mt++) {
            int r0 = mbase + 16 * mt + frow;
            #pragma unroll
            for (int n8 = 0; n8 < 4; n8++) {
                int gc = nbase + 8 * n8 + fcol;
                const float2 wa = *reinterpret_cast<const float2*>(
                    &W[(size_t)r0 * DIN + gc]);
                const float2 wb = *reinterpret_cast<const float2*>(
                    &W[(size_t)(r0 + 8) * DIN + gc]);
                __half2* oh = (__half2*)wh;
                oh[((size_t)r0 * DIN + gc) >> 1] =
                    __floats2half2_rn(acc[mt][n8][0] + wa.x, acc[mt][n8][1] + wa.y);
                oh[((size_t)(r0 + 8) * DIN + gc) >> 1] =
                    __floats2half2_rn(acc[mt][n8][2] + wb.x, acc[mt][n8][3] + wb.y);
            }
        }
        __threadfence();
        __syncwarp();
        if (lane == 0) atomicAdd(&g_whdone[nx >> 7], 1);
    } else {
        #pragma unroll
        for (int mt = 0; mt < 4; mt++) {
            int r0 = mbase + 16 * mt + frow;
            #pragma unroll
            for (int n8 = 0; n8 < 4; n8++) {
                int gc = nbase + 8 * n8 + fcol;
                const float2 bb = *reinterpret_cast<const float2*>(&bias[gc]);
                *reinterpret_cast<float2*>(&outp[(size_t)r0 * DOUT + gc]) =
                    make_float2(acc[mt][n8][0] + bb.x, acc[mt][n8][1] + bb.y);
                *reinterpret_cast<float2*>(&outp[(size_t)(r0 + 8) * DOUT + gc]) =
                    make_float2(acc[mt][n8][2] + bb.x, acc[mt][n8][3] + bb.y);
            }
        }
    }
}

// ======================================================================
// prep kernels
// ======================================================================
__global__ void k_reset() {
    int t = threadIdx.x;
    if (t < NXCHUNK) g_xdone[t] = 0;
    else if (t < NXCHUNK + NSTRIP) g_whdone[t - NXCHUNK] = 0;
}

// x -> fp16, with per-128-row-chunk completion counting.
__global__ void k_x2h(const float4* __restrict__ in, __half2* __restrict__ o, int n4) {
    int i = blockIdx.x * blockDim.x + threadIdx.x;
    if (i < n4) {
        float4 v = in[i];
        o[2 * i]     = __floats2half2_rn(v.x, v.y);
        o[2 * i + 1] = __floats2half2_rn(v.z, v.w);
    }
    __threadfence();
    __syncthreads();
    if (threadIdx.x == 0)
        atomicAdd(&g_xdone[blockIdx.x >> 9], 1);   // 512 CTAs per chunk
}

// merged: Cm[o][er] = h(probs[e]*B[e][o][r]);  At[d][er] = h(A[er][d])
__global__ void k_prep(const float* __restrict__ Bw, const float* __restrict__ probs,
                       const float* __restrict__ A,
                       __half* __restrict__ Cm, __half* __restrict__ At) {
    int idx = blockIdx.x * blockDim.x + threadIdx.x;
    if (idx < DOUT * KLORA) {
        int er = idx & 255, o = idx >> 8;
        int e = er >> 4, r = er & 15;
        Cm[idx] = __float2half_rn(probs[e] * Bw[((size_t)e * DOUT + o) * 16 + r]);
    } else {
        int j = idx - DOUT * KLORA;
        if (j < DIN * KLORA) {
            int d = j & 4095, er = j >> 12;
            At[(size_t)d * KLORA + er] = __float2half_rn(A[(size_t)er * DIN + d]);
        }
    }
}

// ======================================================================
// host side
// ======================================================================
typedef CUresult (*PFN_encodeTiled)(
    CUtensorMap*, CUtensorMapDataType, cuuint32_t, void*,
    const cuuint64_t*, const cuuint64_t*, const cuuint32_t*, const cuuint32_t*,
    CUtensorMapInterleave, CUtensorMapSwizzle, CUtensorMapL2promotion,
    CUtensorMapFloatOOBfill);

static void make_map(PFN_encodeTiled enc, CUtensorMap* m, void* base,
                     unsigned long long kdim, unsigned long long rows) {
    cuuint64_t dims[2]    = {kdim, rows};
    cuuint64_t strides[1] = {kdim * 2};               // fp16
    cuuint32_t box[2]     = {(cuuint32_t)BK, 128u};
    cuuint32_t es[2]      = {1u, 1u};
    enc(m, CU_TENSOR_MAP_DATA_TYPE_FLOAT16, 2, base, dims, strides, box, es,
        CU_TENSOR_MAP_INTERLEAVE_NONE, CU_TENSOR_MAP_SWIZZLE_128B,
        CU_TENSOR_MAP_L2_PROMOTION_L2_128B, CU_TENSOR_MAP_FLOAT_OOB_FILL_NONE);
}

extern "C" void kernel_launch(void* const* d_in, const int* in_sizes, int n_in,
                              void* d_out, int out_size) {
    const float* x     = (const float*)d_in[0];
    const float* W     = (const float*)d_in[1];
    const float* b     = (const float*)d_in[2];
    const float* A     = (const float*)d_in[3];
    const float* Bw    = (const float*)d_in[4];
    const float* probs = (const float*)d_in[5];

    __half *xh, *wh, *cm, *at;
    cudaGetSymbolAddress((void**)&xh, g_xh);
    cudaGetSymbolAddress((void**)&wh, g_wh);
    cudaGetSymbolAddress((void**)&cm, g_cm);
    cudaGetSymbolAddress((void**)&at, g_at);

    void* fp = nullptr;
    cudaDriverEntryPointQueryResult qr;
    cudaGetDriverEntryPointByVersion("cuTensorMapEncodeTiled", &fp, 12000,
                                     cudaEnableDefault, &qr);
    PFN_encodeTiled enc = (PFN_encodeTiled)fp;

    CUtensorMap mapX, mapWh, mapC, mapAt;
    make_map(enc, &mapX,  xh, DIN,   MTOT);
    make_map(enc, &mapWh, wh, DIN,   DOUT);
    make_map(enc, &mapC,  cm, KLORA, DOUT);
    make_map(enc, &mapAt, at, KLORA, DIN);

    cudaFuncSetAttribute(gemm_mega, cudaFuncAttributeMaxDynamicSharedMemorySize,
                         SMEM_G);

    // lazily create side stream + fork/join events on the first (uncaptured)
    // call; replays reuse them so every call does identical work.
    static bool s_init = false;
    static cudaStream_t s_side = 0;
    static cudaEvent_t s_eF = 0, s_eJ = 0;
    if (!s_init) {
        s_init = true;
        if (cudaStreamCreateWithFlags(&s_side, cudaStreamNonBlocking) != cudaSuccess)
            s_side = 0;
        if (s_side) {
            cudaEventCreateWithFlags(&s_eF, cudaEventDisableTiming);
            cudaEventCreateWithFlags(&s_eJ, cudaEventDisableTiming);
        }
    }

    int n4 = (MTOT * DIN) / 4;
    int prepN = (DOUT * KLORA + DIN * KLORA + 255) / 256;

    if (s_side) {
        k_reset<<<1, NXCHUNK + NSTRIP>>>();
        cudaEventRecord(s_eF, 0);
        cudaStreamWaitEvent(s_side, s_eF, 0);
        // side: x -> fp16 (chunk flags)
        k_x2h<<<n4 / 256, 256, 0, s_side>>>((const float4*)x, (__half2*)xh, n4);
        cudaEventRecord(s_eJ, s_side);

        // main: LoRA prep, then mega kernel (W_eff roles first, out roles gated)
        k_prep<<<prepN, 256>>>(Bw, probs, A, cm, at);
        gemm_mega<<<GRIDT, 288, SMEM_G>>>(mapX, mapWh, mapC, mapAt,
                                          (float*)d_out, W, b, wh);
        cudaStreamWaitEvent(0, s_eJ, 0);   // join side stream
    } else {
        k_reset<<<1, NXCHUNK + NSTRIP>>>();
        k_x2h<<<n4 / 256, 256>>>((const float4*)x, (__half2*)xh, n4);
        k_prep<<<prepN, 256>>>(Bw, probs, A, cm, at);
        gemm_mega<<<GRIDT, 288, SMEM_G>>>(mapX, mapWh, mapC, mapAt,
                                          (float*)d_out, W, b, wh);
    }
}

// round 16
// speedup vs baseline: 1.1002x; 1.0023x over previous
#include <cuda_runtime.h>
#include <cuda.h>
#include <cuda_fp16.h>
#include <cstdint>
#include <cstddef>

// ---------------- problem dims ----------------
#define DIN   4096
#define DOUT  4096
#define MTOT  16384            // B_SZ * S
#define KLORA 256              // E * R

#define BK 64                  // 64 fp16 = 128B row = SW128 atom
#define BNX 128
#define NSTG 3
#define SMEM_CTRL 1024
#define SMEM_G (SMEM_CTRL + NSTG * (128 + BNX) * BK * 2)   // 99328

#define NXCHUNK 128            // 128-row chunks of x
#define CTAS_PER_CHUNK 512     // x2h CTAs per chunk
#define NSTRIP 32              // 128-col strips of wh (DIN/128)
#define STRIP_ARRIVALS 256     // 32 role-1 CTAs x 8 warps per strip

#define ROLE1N 1024            // W_eff tiles: (DOUT/128) x (DIN/128)
#define ROLE2N 4096            // out tiles:  (DOUT/128) x (MTOT/128)
#define GRIDT  (ROLE1N + ROLE2N)

// ---------------- scratch (device globals; no allocation allowed) ----------
__device__ __align__(256) __half g_xh[(size_t)MTOT * DIN];   // 128 MB fp16 x
__device__ __align__(256) __half g_wh[(size_t)DOUT * DIN];   //  32 MB fp16 W_eff
__device__ __align__(256) __half g_cm[(size_t)DOUT * KLORA]; //   2 MB probs*B
__device__ __align__(256) __half g_at[(size_t)DIN * KLORA];  //   2 MB A^T
__device__ int g_xdone[NXCHUNK];                             // x2h progress
__device__ int g_whdone[NSTRIP];                             // W_eff strip progress

// ---------------- PTX helpers ----------------
__device__ __forceinline__ uint32_t smem_u32(const void* p) {
    uint32_t a;
    asm("{ .reg .u64 t; cvta.to.shared.u64 t, %1; cvt.u32.u64 %0, t; }"
        : "=r"(a) : "l"(p));
    return a;
}

#define MBARRIER_INIT(addr, cnt) \
    asm volatile("mbarrier.init.shared.b64 [%0], %1;" \
                 :: "r"((uint32_t)(addr)), "r"((uint32_t)(cnt)) : "memory")

#define MBARRIER_EXPECT_TX(addr, bytes) \
    asm volatile("mbarrier.arrive.expect_tx.shared.b64 _, [%0], %1;" \
                 :: "r"((uint32_t)(addr)), "r"((uint32_t)(bytes)) : "memory")

#define MBARRIER_ARRIVE(addr) \
    asm volatile("mbarrier.arrive.shared.b64 _, [%0];" \
                 :: "r"((uint32_t)(addr)) : "memory")

#define MBARRIER_WAIT_PARITY(addr, parity) do { \
    uint32_t _mb = (uint32_t)(addr); \
    uint32_t _pa = (uint32_t)(parity); \
    asm volatile( \
        "{\n\t.reg .pred P1;\n\t" \
        "WL_%=:\n\t" \
        "mbarrier.try_wait.parity.shared.b64 P1, [%0], %1;\n\t" \
        "@P1 bra.uni WD_%=;\n\t" \
        "bra.uni WL_%=;\n\t" \
        "WD_%=:\n\t}" \
        :: "r"(_mb), "r"(_pa) : "memory"); \
} while (0)

#define TMA2D(sa, pmap, cx, cy, mb) \
    asm volatile("cp.async.bulk.tensor.2d.shared::cta.global.tile.mbarrier::complete_tx::bytes " \
                 "[%0], [%1, {%2, %3}], [%4];" \
                 :: "r"((uint32_t)(sa)), "l"(pmap), "r"((int)(cx)), "r"((int)(cy)), \
                    "r"((uint32_t)(mb)) : "memory")

__device__ __forceinline__ void ldsm4(uint32_t* r, uint32_t a) {
    asm volatile("ldmatrix.sync.aligned.m8n8.x4.shared.b16 {%0,%1,%2,%3}, [%4];"
                 : "=r"(r[0]), "=r"(r[1]), "=r"(r[2]), "=r"(r[3]) : "r"(a));
}

__device__ __forceinline__ void mma16816(float* c, const uint32_t* a,
                                         uint32_t b0, uint32_t b1) {
    asm volatile("mma.sync.aligned.m16n8k16.row.col.f32.f16.f16.f32 "
                 "{%0,%1,%2,%3}, {%4,%5,%6,%7}, {%8,%9}, {%0,%1,%2,%3};"
                 : "+f"(c[0]), "+f"(c[1]), "+f"(c[2]), "+f"(c[3])
                 : "r"(a[0]), "r"(a[1]), "r"(a[2]), "r"(a[3]), "r"(b0), "r"(b1));
}

#define BAR_FULL(s)  (sb + 16 + (uint32_t)(s) * 16)
#define BAR_EMPTY(s) (sb + 24 + (uint32_t)(s) * 16)

// ======================================================================
// Mega-kernel: role-1 CTAs (blockIdx < 1024) build W_eff = h(Cm@At^T + W)
// and publish per-128-col-strip flags; role-2 CTAs compute
// out = xh @ W_eff^T + b, gating A-TMA on x-chunk flags and each K-stage's
// B-TMA on the corresponding W_eff strip flag. Role-1s are dispatched
// before role-2s (blockIdx order) => no deadlock.
// 128x128 CTA tile: 8 compute warps (2Mx4N of 64x32) + 1 TMA producer.
// ======================================================================
__global__ __launch_bounds__(288, 2) void gemm_mega(
    const __grid_constant__ CUtensorMap tmX,
    const __grid_constant__ CUtensorMap tmWh,
    const __grid_constant__ CUtensorMap tmC,
    const __grid_constant__ CUtensorMap tmAt,
    float* __restrict__ outp,
    const float* __restrict__ W,
    const float* __restrict__ bias,
    __half* __restrict__ wh)
{
    constexpr int ABYT = 128 * BK * 2;          // 16384
    constexpr int STGB = (128 + BNX) * BK * 2;  // 32768

    extern __shared__ char smem[];
    uint32_t sb = smem_u32(smem);
    int tid = threadIdx.x, wid = tid >> 5, lane = tid & 31;

    int c = blockIdx.x;
    bool r1 = (c < ROLE1N);
    int my, nx, kst;
    const CUtensorMap *pA, *pB;
    if (r1) {
        int n1 = c >> 5, m1 = c & 31;
        my = m1 * 128;  nx = n1 * 128;  kst = KLORA / BK;   // 4
        pA = &tmC;  pB = &tmAt;
    } else {
        int c2 = c - ROLE1N;
        my = (c2 >> 5) * 128;  nx = (c2 & 31) * 128;  kst = DIN / BK;  // 64
        pA = &tmX;  pB = &tmWh;
    }

    if (tid == 0) {
        #pragma unroll
        for (int s = 0; s < NSTG; s++) {
            MBARRIER_INIT(BAR_FULL(s), 1);
            MBARRIER_INIT(BAR_EMPTY(s), 8);
        }
    }
    __syncthreads();

    if (wid == 8) {
        // ---------------- TMA producer (lane 0 only) ----------------
        if (lane == 0) {
            if (!r1) {
                volatile int* vx = &g_xdone[my >> 7];
                while (*vx < CTAS_PER_CHUNK) __nanosleep(128);
                __threadfence();
            }
            int jready = 0;
            int st = 0, ph = 1;
            for (int s = 0; s < kst; s++) {
                if (!r1) {
                    int need = s >> 1;           // wh strip for this K-stage
                    if (jready <= need) {
                        volatile int* vw = &g_whdone[need];
                        while (*vw < STRIP_ARRIVALS) __nanosleep(128);
                        __threadfence();
                        jready = need + 1;
                    }
                }
                MBARRIER_WAIT_PARITY(BAR_EMPTY(st), ph);
                MBARRIER_EXPECT_TX(BAR_FULL(st), STGB);
                uint32_t ab = sb + SMEM_CTRL + st * STGB;
                TMA2D(ab,        pA, s * BK, my, BAR_FULL(st));
                TMA2D(ab + ABYT, pB, s * BK, nx, BAR_FULL(st));
                if (++st == NSTG) { st = 0; ph ^= 1; }
            }
        }
        return;
    }

    // ------- compute warps: 2(M) x 4(N) grid of 64(M) x 32(N) tiles -------
    int wr = wid & 1;           // M offset 64*wr
    int wc = wid >> 1;          // N offset 32*wc
    int r15 = lane & 15, kh = lane >> 4;

    uint32_t aPre[4], aX[4], bPre[2], bX[2];
    #pragma unroll
    for (int t = 0; t < 4; t++) {
        uint32_t arow = (uint32_t)(64 * wr + 16 * t + r15) * 128u;
        aPre[t] = arow;
        aX[t] = (arow >> 3) & 0x70u;
    }
    #pragma unroll
    for (int t = 0; t < 2; t++) {
        uint32_t brow = (uint32_t)(32 * wc + 16 * t + r15) * 128u;
        bPre[t] = ABYT + brow;
        bX[t] = (brow >> 3) & 0x70u;
    }
    uint32_t khb = (uint32_t)kh << 4;

    float acc[4][4][4];
    #pragma unroll
    for (int mt = 0; mt < 4; mt++)
        #pragma unroll
        for (int nt = 0; nt < 4; nt++)
            #pragma unroll
            for (int e = 0; e < 4; e++) acc[mt][nt][e] = 0.0f;

    uint32_t af[2][4][4];
    uint32_t bf[2][4];

    int st = 0, ph = 0;
    for (int s = 0; s < kst; s++) {
        MBARRIER_WAIT_PARITY(BAR_FULL(st), ph);
        uint32_t stbase = sb + SMEM_CTRL + (uint32_t)st * STGB;

        {
            uint32_t kbits = khb;
            #pragma unroll
            for (int mt = 0; mt < 4; mt++)
                ldsm4(af[0][mt], stbase + aPre[mt] + (kbits ^ aX[mt]));
        }
        #pragma unroll
        for (int kk = 0; kk < 4; kk++) {
            int cur = kk & 1;
            uint32_t kbits = ((uint32_t)kk << 5) | khb;
            if (kk < 3) {
                uint32_t kb2 = ((uint32_t)(kk + 1) << 5) | khb;
                #pragma unroll
                for (int mt = 0; mt < 4; mt++)
                    ldsm4(af[cur ^ 1][mt], stbase + aPre[mt] + (kb2 ^ aX[mt]));
            }
            #pragma unroll
            for (int nt = 0; nt < 2; nt++)
                ldsm4(bf[nt], stbase + bPre[nt] + (kbits ^ bX[nt]));
            #pragma unroll
            for (int mt = 0; mt < 4; mt++)
                #pragma unroll
                for (int n8 = 0; n8 < 4; n8++)
                    mma16816(acc[mt][n8], af[cur][mt],
                             bf[n8 >> 1][n8 & 1], bf[n8 >> 1][(n8 & 1) + 2]);
        }
        if (lane == 0) MBARRIER_ARRIVE(BAR_EMPTY(st));
        if (++st == NSTG) { st = 0; ph ^= 1; }
    }

    // ---------------- epilogue ----------------
    int mbase = my + 64 * wr;
    int nbase = nx + 32 * wc;
    int frow = lane >> 2, fcol = (lane & 3) * 2;

    if (r1) {
        // W_eff = h(acc + W); publish strip flag
        #pragma unroll
        for (int mt = 0; mt < 4; mt++) {
            int r0 = mbase + 16 * mt + frow;
            #pragma unroll
            for (int n8 = 0; n8 < 4; n8++) {
                int gc = nbase + 8 * n8 + fcol;
                const float2 wa = *reinterpret_cast<const float2*>(
                    &W[(size_t)r0 * DIN + gc]);
                const float2 wb = *reinterpret_cast<const float2*>(
                    &W[(size_t)(r0 + 8) * DIN + gc]);
                __half2* oh = (__half2*)wh;
                oh[((size_t)r0 * DIN + gc) >> 1] =
                    __floats2half2_rn(acc[mt][n8][0] + wa.x, acc[mt][n8][1] + wa.y);
                oh[((size_t)(r0 + 8) * DIN + gc) >> 1] =
                    __floats2half2_rn(acc[mt][n8][2] + wb.x, acc[mt][n8][3] + wb.y);
            }
        }
        __threadfence();
        __syncwarp();
        if (lane == 0) atomicAdd(&g_whdone[nx >> 7], 1);
    } else {
        #pragma unroll
        for (int mt = 0; mt < 4; mt++) {
            int r0 = mbase + 16 * mt + frow;
            #pragma unroll
            for (int n8 = 0; n8 < 4; n8++) {
                int gc = nbase + 8 * n8 + fcol;
                const float2 bb = *reinterpret_cast<const float2*>(&bias[gc]);
                *reinterpret_cast<float2*>(&outp[(size_t)r0 * DOUT + gc]) =
                    make_float2(acc[mt][n8][0] + bb.x, acc[mt][n8][1] + bb.y);
                *reinterpret_cast<float2*>(&outp[(size_t)(r0 + 8) * DOUT + gc]) =
                    make_float2(acc[mt][n8][2] + bb.x, acc[mt][n8][3] + bb.y);
            }
        }
    }
}

// ======================================================================
// prep kernels
// ======================================================================
__global__ void k_reset() {
    int t = threadIdx.x;
    if (t < NXCHUNK) g_xdone[t] = 0;
    else if (t < NXCHUNK + NSTRIP) g_whdone[t - NXCHUNK] = 0;
}

// x -> fp16, with per-128-row-chunk completion counting.
__global__ void k_x2h(const float4* __restrict__ in, __half2* __restrict__ o, int n4) {
    int i = blockIdx.x * blockDim.x + threadIdx.x;
    if (i < n4) {
        float4 v = in[i];
        o[2 * i]     = __floats2half2_rn(v.x, v.y);
        o[2 * i + 1] = __floats2half2_rn(v.z, v.w);
    }
    __threadfence();
    __syncthreads();
    if (threadIdx.x == 0)
        atomicAdd(&g_xdone[blockIdx.x >> 9], 1);   // 512 CTAs per chunk
}

// merged: Cm[o][er] = h(probs[e]*B[e][o][r]);  At[d][er] = h(A[er][d])
__global__ void k_prep(const float* __restrict__ Bw, const float* __restrict__ probs,
                       const float* __restrict__ A,
                       __half* __restrict__ Cm, __half* __restrict__ At) {
    int idx = blockIdx.x * blockDim.x + threadIdx.x;
    if (idx < DOUT * KLORA) {
        int er = idx & 255, o = idx >> 8;
        int e = er >> 4, r = er & 15;
        Cm[idx] = __float2half_rn(probs[e] * Bw[((size_t)e * DOUT + o) * 16 + r]);
    } else {
        int j = idx - DOUT * KLORA;
        if (j < DIN * KLORA) {
            int d = j & 4095, er = j >> 12;
            At[(size_t)d * KLORA + er] = __float2half_rn(A[(size_t)er * DIN + d]);
        }
    }
}

// ======================================================================
// host side
// ======================================================================
typedef CUresult (*PFN_encodeTiled)(
    CUtensorMap*, CUtensorMapDataType, cuuint32_t, void*,
    const cuuint64_t*, const cuuint64_t*, const cuuint32_t*, const cuuint32_t*,
    CUtensorMapInterleave, CUtensorMapSwizzle, CUtensorMapL2promotion,
    CUtensorMapFloatOOBfill);

static void make_map(PFN_encodeTiled enc, CUtensorMap* m, void* base,
                     unsigned long long kdim, unsigned long long rows) {
    cuuint64_t dims[2]    = {kdim, rows};
    cuuint64_t strides[1] = {kdim * 2};               // fp16
    cuuint32_t box[2]     = {(cuuint32_t)BK, 128u};
    cuuint32_t es[2]      = {1u, 1u};
    enc(m, CU_TENSOR_MAP_DATA_TYPE_FLOAT16, 2, base, dims, strides, box, es,
        CU_TENSOR_MAP_INTERLEAVE_NONE, CU_TENSOR_MAP_SWIZZLE_128B,
        CU_TENSOR_MAP_L2_PROMOTION_L2_128B, CU_TENSOR_MAP_FLOAT_OOB_FILL_NONE);
}

extern "C" void kernel_launch(void* const* d_in, const int* in_sizes, int n_in,
                              void* d_out, int out_size) {
    const float* x     = (const float*)d_in[0];
    const float* W     = (const float*)d_in[1];
    const float* b     = (const float*)d_in[2];
    const float* A     = (const float*)d_in[3];
    const float* Bw    = (const float*)d_in[4];
    const float* probs = (const float*)d_in[5];

    __half *xh, *wh, *cm, *at;
    cudaGetSymbolAddress((void**)&xh, g_xh);
    cudaGetSymbolAddress((void**)&wh, g_wh);
    cudaGetSymbolAddress((void**)&cm, g_cm);
    cudaGetSymbolAddress((void**)&at, g_at);

    void* fp = nullptr;
    cudaDriverEntryPointQueryResult qr;
    cudaGetDriverEntryPointByVersion("cuTensorMapEncodeTiled", &fp, 12000,
                                     cudaEnableDefault, &qr);
    PFN_encodeTiled enc = (PFN_encodeTiled)fp;

    CUtensorMap mapX, mapWh, mapC, mapAt;
    make_map(enc, &mapX,  xh, DIN,   MTOT);
    make_map(enc, &mapWh, wh, DIN,   DOUT);
    make_map(enc, &mapC,  cm, KLORA, DOUT);
    make_map(enc, &mapAt, at, KLORA, DIN);

    cudaFuncSetAttribute(gemm_mega, cudaFuncAttributeMaxDynamicSharedMemorySize,
                         SMEM_G);

    // lazily create side stream + fork/join events on the first (uncaptured)
    // call; replays reuse them so every call does identical work.
    static bool s_init = false;
    static cudaStream_t s_side = 0;
    static cudaEvent_t s_eF = 0, s_eJ = 0;
    if (!s_init) {
        s_init = true;
        if (cudaStreamCreateWithFlags(&s_side, cudaStreamNonBlocking) != cudaSuccess)
            s_side = 0;
        if (s_side) {
            cudaEventCreateWithFlags(&s_eF, cudaEventDisableTiming);
            cudaEventCreateWithFlags(&s_eJ, cudaEventDisableTiming);
        }
    }

    int n4 = (MTOT * DIN) / 4;
    int prepN = (DOUT * KLORA + DIN * KLORA + 255) / 256;

    if (s_side) {
        k_reset<<<1, NXCHUNK + NSTRIP>>>();
        cudaEventRecord(s_eF, 0);
        cudaStreamWaitEvent(s_side, s_eF, 0);
        // side: x -> fp16 (chunk flags)
        k_x2h<<<n4 / 256, 256, 0, s_side>>>((const float4*)x, (__half2*)xh, n4);
        cudaEventRecord(s_eJ, s_side);

        // main: LoRA prep, then mega kernel (W_eff roles first, out roles gated)
        k_prep<<<prepN, 256>>>(Bw, probs, A, cm, at);
        gemm_mega<<<GRIDT, 288, SMEM_G>>>(mapX, mapWh, mapC, mapAt,
                                          (float*)d_out, W, b, wh);
        cudaStreamWaitEvent(0, s_eJ, 0);   // join side stream
    } else {
        k_reset<<<1, NXCHUNK + NSTRIP>>>();
        k_x2h<<<n4 / 256, 256>>>((const float4*)x, (__half2*)xh, n4);
        k_prep<<<prepN, 256>>>(Bw, probs, A, cm, at);
        gemm_mega<<<GRIDT, 288, SMEM_G>>>(mapX, mapWh, mapC, mapAt,
                                          (float*)d_out, W, b, wh);
    }
}